// round 9
// baseline (speedup 1.0000x reference)
#include <cuda_runtime.h>
#include <math.h>

// OmegaRule: B=8, L=8192, D=256, W=64 -> NW=128 windows, T=B*W=512 rows/window.
#define BB 8
#define LL 8192
#define DD 256
#define WW 64
#define NW 128
#define TT 512
#define CH 16    // chunks
#define CS 8     // windows per chunk (CH*CS == NW)
#define MATSZ (DD * DD)
#define RM 8     // M-rows (and P-rows) per CTA in kA

// Scratch (device globals; no allocation allowed).
__device__ float g_Skk[NW * MATSZ];
__device__ float g_Svk[NW * MATSZ];
__device__ float g_Ms [NW * MATSZ];
__device__ float g_P  [NW * MATSZ];
__device__ float g_TP0[CH * MATSZ];
__device__ float g_TP1[CH * MATSZ];
__device__ float g_TS0[CH * MATSZ];
__device__ float g_TS1[CH * MATSZ];

typedef unsigned long long u64;
__device__ __forceinline__ void ffma2(u64& acc, u64 a, u64 b) {
    asm("fma.rn.f32x2 %0, %1, %2, %0;" : "+l"(acc) : "l"(a), "l"(b));
}
__device__ __forceinline__ u64 pack2f(float x, float y) {
    u64 r; asm("mov.b64 %0, {%1, %2};" : "=l"(r) : "f"(x), "f"(y)); return r;
}
__device__ __forceinline__ void unpack2f(u64 v, float& x, float& y) {
    asm("mov.b64 {%0, %1}, %2;" : "=f"(x), "=f"(y) : "l"(v));
}
__device__ __forceinline__ float hsum2(u64 v) {
    float x, y; unpack2f(v, x, y); return x + y;
}

// ---------------------------------------------------------------------------
// K1: per-window moment matrices (R5 version: symmetry + register prefetch).
//   Skk[n] = sum_t g_t k_t k_t^T   (computed for ib<=jb, mirrored)
//   Svk[n] = sum_t g_t v_t k_t^T   (all 16 tiles)
// ---------------------------------------------------------------------------
__global__ __launch_bounds__(256) void k1_moments(
    const float* __restrict__ keys,
    const float* __restrict__ values,
    const float* __restrict__ gammas)
{
    __shared__ float4 sGK[16][16];
    __shared__ float4 sGV[16][16];
    __shared__ float4 sK [16][16];

    const int n   = blockIdx.y;
    const int ib  = blockIdx.x >> 2;
    const int jb  = blockIdx.x & 3;
    const bool doSkk = (ib <= jb);
    const int tid = threadIdx.x;
    const int tr  = tid >> 4;
    const int tc  = tid & 15;
    const int tx  = tid & 15;
    const int ty  = tid >> 4;

    float acc1[4][4], acc2[4][4];
    #pragma unroll
    for (int r = 0; r < 4; ++r)
        #pragma unroll
        for (int c = 0; c < 4; ++c) { acc1[r][c] = 0.f; acc2[r][c] = 0.f; }

    float g; float4 kx, vx, ky;
    {
        const int t = tr;
        const int b = t >> 6;
        const int w = t & 63;
        const long row = ((long)b * LL + (long)n * WW + w) * DD;
        g  = __ldg(&gammas[(long)b * LL + (long)n * WW + w]);
        vx = *(const float4*)(values + row + ib * 64 + tc * 4);
        ky = *(const float4*)(keys   + row + jb * 64 + tc * 4);
        kx = *(const float4*)(keys   + row + ib * 64 + tc * 4);
    }

    for (int ch = 0; ch < TT / 16; ++ch) {
        sGV[tr][tc] = make_float4(g * vx.x, g * vx.y, g * vx.z, g * vx.w);
        sK [tr][tc] = ky;
        if (doSkk)
            sGK[tr][tc] = make_float4(g * kx.x, g * kx.y, g * kx.z, g * kx.w);
        __syncthreads();

        if (ch < TT / 16 - 1) {
            const int t = (ch + 1) * 16 + tr;
            const int b = t >> 6;
            const int w = t & 63;
            const long row = ((long)b * LL + (long)n * WW + w) * DD;
            g  = __ldg(&gammas[(long)b * LL + (long)n * WW + w]);
            vx = *(const float4*)(values + row + ib * 64 + tc * 4);
            ky = *(const float4*)(keys   + row + jb * 64 + tc * 4);
            if (doSkk) kx = *(const float4*)(keys + row + ib * 64 + tc * 4);
        }

        if (doSkk) {
            #pragma unroll
            for (int tk = 0; tk < 16; ++tk) {
                float4 a1 = sGK[tk][ty];
                float4 a2 = sGV[tk][ty];
                float4 bb = sK [tk][tx];
                float av1[4] = {a1.x, a1.y, a1.z, a1.w};
                float av2[4] = {a2.x, a2.y, a2.z, a2.w};
                float bv [4] = {bb.x, bb.y, bb.z, bb.w};
                #pragma unroll
                for (int r = 0; r < 4; ++r)
                    #pragma unroll
                    for (int c = 0; c < 4; ++c) {
                        acc1[r][c] += av1[r] * bv[c];
                        acc2[r][c] += av2[r] * bv[c];
                    }
            }
        } else {
            #pragma unroll
            for (int tk = 0; tk < 16; ++tk) {
                float4 a2 = sGV[tk][ty];
                float4 bb = sK [tk][tx];
                float av2[4] = {a2.x, a2.y, a2.z, a2.w};
                float bv [4] = {bb.x, bb.y, bb.z, bb.w};
                #pragma unroll
                for (int r = 0; r < 4; ++r)
                    #pragma unroll
                    for (int c = 0; c < 4; ++c)
                        acc2[r][c] += av2[r] * bv[c];
            }
        }
        __syncthreads();
    }

    float* svk = g_Svk + (long)n * MATSZ;
    #pragma unroll
    for (int r = 0; r < 4; ++r) {
        const int x  = ib * 64 + ty * 4 + r;
        const int y0 = jb * 64 + tx * 4;
        *(float4*)(svk + (long)x * DD + y0) =
            make_float4(acc2[r][0], acc2[r][1], acc2[r][2], acc2[r][3]);
    }
    if (doSkk) {
        float* skk = g_Skk + (long)n * MATSZ;
        #pragma unroll
        for (int r = 0; r < 4; ++r) {
            const int x  = ib * 64 + ty * 4 + r;
            const int y0 = jb * 64 + tx * 4;
            *(float4*)(skk + (long)x * DD + y0) =
                make_float4(acc1[r][0], acc1[r][1], acc1[r][2], acc1[r][3]);
        }
        if (ib < jb) {
            #pragma unroll
            for (int r = 0; r < 4; ++r)
                #pragma unroll
                for (int c = 0; c < 4; ++c) {
                    const int x = ib * 64 + ty * 4 + r;
                    const int y = jb * 64 + tx * 4 + c;
                    skk[(long)y * DD + x] = acc1[r][c];
                }
        }
    }
}

// ---------------------------------------------------------------------------
// Phase A: per-chunk local scan + prefix products. Conflict-free column
// layout (thread j owns column j; srow reads are warp-broadcast).
// RM=8 M-rows + 8 P-rows per CTA -> 2x Skk reuse vs R5.
// Last window also writes the (P,S) chunk summary into tree buffer 0.
// grid = (DD/RM = 32 row-groups, CH chunks), block = 256.
// ---------------------------------------------------------------------------
__global__ __launch_bounds__(256) void kA_local(const float* __restrict__ alpha_p)
{
    __shared__ float srow[2 * RM][DD];   // rows 0-7: M, rows 8-15: P
    const int j  = threadIdx.x;
    const int c  = blockIdx.y;
    const int o0 = blockIdx.x * RM;
    const float a = 1.f / (1.f + expf(-alpha_p[0]));

    #pragma unroll
    for (int r = 0; r < RM; ++r) {
        srow[r][j] = 0.f;
        srow[RM + r][j] = (j == o0 + r) ? 1.f : 0.f;
    }
    __syncthreads();

    for (int s = 0; s < CS; ++s) {
        const int n = c * CS + s;
        const float* skk = g_Skk + (long)n * MATSZ;
        const float* svk = g_Svk + (long)n * MATSZ;

        float sv[RM];
        #pragma unroll
        for (int r = 0; r < RM; ++r) sv[r] = svk[(long)(o0 + r) * DD + j];

        u64 accM[RM] = {0,0,0,0,0,0,0,0};
        u64 accP[RM] = {0,0,0,0,0,0,0,0};

        float sb[16];
        #pragma unroll
        for (int u = 0; u < 16; ++u) sb[u] = skk[(long)u * DD + j];

        for (int blk = 0; blk < 16; ++blk) {
            float sn[16];
            if (blk < 15) {
                const float* p = skk + (long)(blk + 1) * 16 * DD + j;
                #pragma unroll
                for (int u = 0; u < 16; ++u) sn[u] = p[(long)u * DD];
            } else {
                #pragma unroll
                for (int u = 0; u < 16; ++u) sn[u] = 0.f;
            }
            u64 sp[8];
            #pragma unroll
            for (int p = 0; p < 8; ++p) sp[p] = pack2f(sb[2 * p], sb[2 * p + 1]);

            const int db = blk * 16;
            #pragma unroll
            for (int r = 0; r < RM; ++r) {
                const u64* mrow = (const u64*)&srow[r][db];
                #pragma unroll
                for (int p = 0; p < 8; ++p) ffma2(accM[r], mrow[p], sp[p]);
            }
            #pragma unroll
            for (int r = 0; r < RM; ++r) {
                const u64* prow = (const u64*)&srow[RM + r][db];
                #pragma unroll
                for (int p = 0; p < 8; ++p) ffma2(accP[r], prow[p], sp[p]);
            }
            #pragma unroll
            for (int u = 0; u < 16; ++u) sb[u] = sn[u];
        }

        float nM[RM], nP[RM];
        #pragma unroll
        for (int r = 0; r < RM; ++r) {
            nM[r] = a * srow[r][j] - hsum2(accM[r]) + sv[r];
            nP[r] = a * srow[RM + r][j] - hsum2(accP[r]);
        }
        __syncthreads();
        float* ms = g_Ms + (long)n * MATSZ;
        float* pp = g_P  + (long)n * MATSZ;
        #pragma unroll
        for (int r = 0; r < RM; ++r) {
            srow[r][j] = nM[r];
            srow[RM + r][j] = nP[r];
            ms[(long)(o0 + r) * DD + j] = nM[r];
            pp[(long)(o0 + r) * DD + j] = nP[r];
        }
        if (s == CS - 1) {   // fused kT_init
            float* ts = g_TS0 + (long)c * MATSZ;
            float* tp = g_TP0 + (long)c * MATSZ;
            #pragma unroll
            for (int r = 0; r < RM; ++r) {
                ts[(long)(o0 + r) * DD + j] = nM[r];
                tp[(long)(o0 + r) * DD + j] = nP[r];
            }
        }
        __syncthreads();
    }
}

// ---------------------------------------------------------------------------
// Tree level (Kogge-Stone over chunk summaries), R5 scalar microkernel:
//   combine(first,second) = (P1@P2, S1@P2 + S2)
// dst_c = combine(src_{c-stride}, src_c) for c>=stride, else copy.
// onlyS=1 at the last level (P result unused).
// ---------------------------------------------------------------------------
__global__ __launch_bounds__(256) void kT_combine(int stride, int srcIdx, int onlyS)
{
    const float* srcP = srcIdx ? g_TP1 : g_TP0;
    const float* srcS = srcIdx ? g_TS1 : g_TS0;
    float*       dstP = srcIdx ? g_TP0 : g_TP1;
    float*       dstS = srcIdx ? g_TS0 : g_TS1;

    const int c   = blockIdx.y;
    const int isS = onlyS ? 1 : blockIdx.z;
    const int ib  = blockIdx.x >> 2;
    const int jb  = blockIdx.x & 3;
    const int tid = threadIdx.x;

    const float* srcM = isS ? srcS : srcP;
    float*       dstM = isS ? dstS : dstP;

    if (c < stride) {   // pass-through copy
        const int lr = tid >> 2;
        const int lc = tid & 3;
        const long base = (long)c * MATSZ;
        #pragma unroll
        for (int it = 0; it < 4; ++it) {
            const long off = base + (long)(ib * 64 + lr) * DD + jb * 64 + (lc + it * 4) * 4;
            *(float4*)(dstM + off) = *(const float4*)(srcM + off);
        }
        return;
    }

    __shared__ float sA[16][68];
    __shared__ float sB[16][68];

    const int lr = tid >> 2;
    const int lc = tid & 3;
    const int pr = tid >> 4;
    const int pc = tid & 15;
    const int tx = tid & 15;
    const int ty = tid >> 4;

    const float* A  = srcM + (long)(c - stride) * MATSZ;
    const float* Bm = srcP + (long)c * MATSZ;
    float*       Dm = dstM + (long)c * MATSZ;

    float acc[4][4];
    #pragma unroll
    for (int r = 0; r < 4; ++r)
        #pragma unroll
        for (int q = 0; q < 4; ++q) acc[r][q] = 0.f;

    const long arow = (long)(ib * 64 + lr) * DD;

    float4 av = *(const float4*)(A + arow + lc * 4);
    float4 bv = *(const float4*)(Bm + (long)pr * DD + jb * 64 + pc * 4);

    for (int ch = 0; ch < 16; ++ch) {
        sA[lc * 4 + 0][lr] = av.x; sA[lc * 4 + 1][lr] = av.y;
        sA[lc * 4 + 2][lr] = av.z; sA[lc * 4 + 3][lr] = av.w;
        sB[pr][pc * 4 + 0] = bv.x; sB[pr][pc * 4 + 1] = bv.y;
        sB[pr][pc * 4 + 2] = bv.z; sB[pr][pc * 4 + 3] = bv.w;
        __syncthreads();

        if (ch < 15) {
            av = *(const float4*)(A + arow + (ch + 1) * 16 + lc * 4);
            bv = *(const float4*)(Bm + (long)((ch + 1) * 16 + pr) * DD + jb * 64 + pc * 4);
        }

        #pragma unroll
        for (int dk = 0; dk < 16; ++dk) {
            float aw[4], bw[4];
            #pragma unroll
            for (int r = 0; r < 4; ++r) aw[r] = sA[dk][ty * 4 + r];
            #pragma unroll
            for (int q = 0; q < 4; ++q) bw[q] = sB[dk][tx * 4 + q];
            #pragma unroll
            for (int r = 0; r < 4; ++r)
                #pragma unroll
                for (int q = 0; q < 4; ++q) acc[r][q] += aw[r] * bw[q];
        }
        __syncthreads();
    }

    const float* C0 = srcS + (long)c * MATSZ;
    #pragma unroll
    for (int r = 0; r < 4; ++r) {
        const long off = (long)(ib * 64 + ty * 4 + r) * DD + jb * 64 + tx * 4;
        float4 res = make_float4(acc[r][0], acc[r][1], acc[r][2], acc[r][3]);
        if (isS) {
            float4 cc = *(const float4*)(C0 + off);
            res.x += cc.x; res.y += cc.y; res.z += cc.z; res.w += cc.w;
        }
        *(float4*)(Dm + off) = res;
    }
}

// ---------------------------------------------------------------------------
// Phase C: fix-up GEMMs: Ms[n] += E_{c-1} @ P_n for chunks 1..CH-1 (R5 version).
// ---------------------------------------------------------------------------
__global__ __launch_bounds__(256) void kC_fix()
{
    __shared__ float sE[16][68];
    __shared__ float sP[16][68];

    const int nw  = blockIdx.y + CS;
    const int c   = nw / CS;
    const int ib  = blockIdx.x >> 2;
    const int jb  = blockIdx.x & 3;
    const int tid = threadIdx.x;
    const int lr  = tid >> 2;
    const int lc  = tid & 3;
    const int pr  = tid >> 4;
    const int pc  = tid & 15;
    const int tx  = tid & 15;
    const int ty  = tid >> 4;

    const float* E = g_TS0 + (long)(c - 1) * MATSZ;
    const float* P = g_P + (long)nw * MATSZ;
    float*      Ms = g_Ms + (long)nw * MATSZ;

    float acc[4][4];
    #pragma unroll
    for (int r = 0; r < 4; ++r)
        #pragma unroll
        for (int q = 0; q < 4; ++q) acc[r][q] = 0.f;

    const long erow = (long)(ib * 64 + lr) * DD;

    float4 ev = *(const float4*)(E + erow + lc * 4);
    float4 pv = *(const float4*)(P + (long)pr * DD + jb * 64 + pc * 4);

    for (int ch = 0; ch < 16; ++ch) {
        sE[lc * 4 + 0][lr] = ev.x; sE[lc * 4 + 1][lr] = ev.y;
        sE[lc * 4 + 2][lr] = ev.z; sE[lc * 4 + 3][lr] = ev.w;
        sP[pr][pc * 4 + 0] = pv.x; sP[pr][pc * 4 + 1] = pv.y;
        sP[pr][pc * 4 + 2] = pv.z; sP[pr][pc * 4 + 3] = pv.w;
        __syncthreads();

        if (ch < 15) {
            ev = *(const float4*)(E + erow + (ch + 1) * 16 + lc * 4);
            pv = *(const float4*)(P + (long)((ch + 1) * 16 + pr) * DD + jb * 64 + pc * 4);
        }

        #pragma unroll
        for (int dk = 0; dk < 16; ++dk) {
            float aw[4], bw[4];
            #pragma unroll
            for (int r = 0; r < 4; ++r) aw[r] = sE[dk][ty * 4 + r];
            #pragma unroll
            for (int q = 0; q < 4; ++q) bw[q] = sP[dk][tx * 4 + q];
            #pragma unroll
            for (int r = 0; r < 4; ++r)
                #pragma unroll
                for (int q = 0; q < 4; ++q) acc[r][q] += aw[r] * bw[q];
        }
        __syncthreads();
    }

    #pragma unroll
    for (int r = 0; r < 4; ++r) {
        float* dst = Ms + (long)(ib * 64 + ty * 4 + r) * DD + jb * 64 + tx * 4;
        float4 old = *(const float4*)dst;
        *(float4*)dst = make_float4(old.x + acc[r][0], old.y + acc[r][1],
                                    old.z + acc[r][2], old.w + acc[r][3]);
    }
}

// ---------------------------------------------------------------------------
// K3: retrieval. out[t][o] = sum_d q[t][d] * Ms[n][o][d]  (R5 version)
// ---------------------------------------------------------------------------
__global__ __launch_bounds__(256) void k3_out(
    const float* __restrict__ queries, float* __restrict__ out)
{
    __shared__ float sQ[16][68];
    __shared__ float sM[16][68];

    const int n   = blockIdx.y;
    const int tb  = blockIdx.x >> 2;
    const int ob  = blockIdx.x & 3;
    const int tid = threadIdx.x;
    const int lr  = tid >> 2;
    const int lc  = tid & 3;
    const int tx  = tid & 15;
    const int ty  = tid >> 4;

    const float* Ms = g_Ms + (long)n * MATSZ;

    float acc[4][4];
    #pragma unroll
    for (int r = 0; r < 4; ++r)
        #pragma unroll
        for (int c = 0; c < 4; ++c) acc[r][c] = 0.f;

    const int t_ld = tb * 64 + lr;
    const int b_ld = t_ld >> 6;
    const int w_ld = t_ld & 63;
    const long qrow = ((long)b_ld * LL + (long)n * WW + w_ld) * DD;
    const long mrow = (long)(ob * 64 + lr) * DD;

    float4 qv = *(const float4*)(queries + qrow + lc * 4);
    float4 mv = *(const float4*)(Ms + mrow + lc * 4);

    for (int ch = 0; ch < 16; ++ch) {
        sQ[lc * 4 + 0][lr] = qv.x; sQ[lc * 4 + 1][lr] = qv.y;
        sQ[lc * 4 + 2][lr] = qv.z; sQ[lc * 4 + 3][lr] = qv.w;
        sM[lc * 4 + 0][lr] = mv.x; sM[lc * 4 + 1][lr] = mv.y;
        sM[lc * 4 + 2][lr] = mv.z; sM[lc * 4 + 3][lr] = mv.w;
        __syncthreads();

        if (ch < 15) {
            qv = *(const float4*)(queries + qrow + (ch + 1) * 16 + lc * 4);
            mv = *(const float4*)(Ms + mrow + (ch + 1) * 16 + lc * 4);
        }

        #pragma unroll
        for (int dk = 0; dk < 16; ++dk) {
            float aw[4], bw[4];
            #pragma unroll
            for (int r = 0; r < 4; ++r) aw[r] = sQ[dk][ty * 4 + r];
            #pragma unroll
            for (int c = 0; c < 4; ++c) bw[c] = sM[dk][tx * 4 + c];
            #pragma unroll
            for (int r = 0; r < 4; ++r)
                #pragma unroll
                for (int c = 0; c < 4; ++c) acc[r][c] += aw[r] * bw[c];
        }
        __syncthreads();
    }

    #pragma unroll
    for (int r = 0; r < 4; ++r) {
        const int t = tb * 64 + ty * 4 + r;
        const int b = t >> 6;
        const int w = t & 63;
        const long addr = ((long)b * LL + (long)n * WW + w) * DD + ob * 64 + tx * 4;
        *(float4*)(out + addr) = make_float4(acc[r][0], acc[r][1], acc[r][2], acc[r][3]);
    }
}

// ---------------------------------------------------------------------------
extern "C" void kernel_launch(void* const* d_in, const int* in_sizes, int n_in,
                              void* d_out, int out_size)
{
    const float* keys    = (const float*)d_in[0];
    const float* values  = (const float*)d_in[1];
    const float* queries = (const float*)d_in[2];
    const float* gammas  = (const float*)d_in[3];
    const float* alpha   = (const float*)d_in[4];
    float* out = (float*)d_out;

    k1_moments<<<dim3(16, NW), 256>>>(keys, values, gammas);
    kA_local<<<dim3(DD / RM, CH), 256>>>(alpha);
    kT_combine<<<dim3(16, CH, 2), 256>>>(1, 0, 0);  // buf0 -> buf1
    kT_combine<<<dim3(16, CH, 2), 256>>>(2, 1, 0);  // buf1 -> buf0
    kT_combine<<<dim3(16, CH, 2), 256>>>(4, 0, 0);  // buf0 -> buf1
    kT_combine<<<dim3(16, CH, 1), 256>>>(8, 1, 1);  // buf1 -> buf0, S only
    kC_fix<<<dim3(16, NW - CS), 256>>>();
    k3_out<<<dim3(32, NW), 256>>>(queries, out);
}

// round 10
// speedup vs baseline: 1.2919x; 1.2919x over previous
#include <cuda_runtime.h>
#include <math.h>

// OmegaRule: B=8, L=8192, D=256, W=64 -> NW=128 windows, T=B*W=512 rows/window.
#define BB 8
#define LL 8192
#define DD 256
#define WW 64
#define NW 128
#define TT 512
#define CH 16    // chunks
#define CS 8     // windows per chunk (CH*CS == NW)
#define MATSZ (DD * DD)

// Scratch (device globals; no allocation allowed).
__device__ float g_Skk[NW * MATSZ];
__device__ float g_Svk[NW * MATSZ];
__device__ float g_Ms [NW * MATSZ];
__device__ float g_P  [NW * MATSZ];
__device__ float g_TP0[CH * MATSZ];
__device__ float g_TP1[CH * MATSZ];
__device__ float g_TS0[CH * MATSZ];
__device__ float g_TS1[CH * MATSZ];

typedef unsigned long long u64;
__device__ __forceinline__ void ffma2(u64& acc, u64 a, u64 b) {
    asm("fma.rn.f32x2 %0, %1, %2, %0;" : "+l"(acc) : "l"(a), "l"(b));
}
__device__ __forceinline__ u64 pack2f(float x, float y) {
    u64 r; asm("mov.b64 %0, {%1, %2};" : "=l"(r) : "f"(x), "f"(y)); return r;
}
__device__ __forceinline__ void unpack2f(u64 v, float& x, float& y) {
    asm("mov.b64 {%0, %1}, %2;" : "=f"(x), "=f"(y) : "l"(v));
}
__device__ __forceinline__ float hsum2(u64 v) {
    float x, y; unpack2f(v, x, y); return x + y;
}

// ---------------------------------------------------------------------------
// K1: per-window moment matrices (R5 version: symmetry + register prefetch).
//   Skk[n] = sum_t g_t k_t k_t^T   (computed for ib<=jb, mirrored)
//   Svk[n] = sum_t g_t v_t k_t^T   (all 16 tiles)
// ---------------------------------------------------------------------------
__global__ __launch_bounds__(256) void k1_moments(
    const float* __restrict__ keys,
    const float* __restrict__ values,
    const float* __restrict__ gammas)
{
    __shared__ float4 sGK[16][16];
    __shared__ float4 sGV[16][16];
    __shared__ float4 sK [16][16];

    const int n   = blockIdx.y;
    const int ib  = blockIdx.x >> 2;
    const int jb  = blockIdx.x & 3;
    const bool doSkk = (ib <= jb);
    const int tid = threadIdx.x;
    const int tr  = tid >> 4;
    const int tc  = tid & 15;
    const int tx  = tid & 15;
    const int ty  = tid >> 4;

    float acc1[4][4], acc2[4][4];
    #pragma unroll
    for (int r = 0; r < 4; ++r)
        #pragma unroll
        for (int c = 0; c < 4; ++c) { acc1[r][c] = 0.f; acc2[r][c] = 0.f; }

    float g; float4 kx, vx, ky;
    {
        const int t = tr;
        const int b = t >> 6;
        const int w = t & 63;
        const long row = ((long)b * LL + (long)n * WW + w) * DD;
        g  = __ldg(&gammas[(long)b * LL + (long)n * WW + w]);
        vx = *(const float4*)(values + row + ib * 64 + tc * 4);
        ky = *(const float4*)(keys   + row + jb * 64 + tc * 4);
        kx = *(const float4*)(keys   + row + ib * 64 + tc * 4);
    }

    for (int ch = 0; ch < TT / 16; ++ch) {
        sGV[tr][tc] = make_float4(g * vx.x, g * vx.y, g * vx.z, g * vx.w);
        sK [tr][tc] = ky;
        if (doSkk)
            sGK[tr][tc] = make_float4(g * kx.x, g * kx.y, g * kx.z, g * kx.w);
        __syncthreads();

        if (ch < TT / 16 - 1) {
            const int t = (ch + 1) * 16 + tr;
            const int b = t >> 6;
            const int w = t & 63;
            const long row = ((long)b * LL + (long)n * WW + w) * DD;
            g  = __ldg(&gammas[(long)b * LL + (long)n * WW + w]);
            vx = *(const float4*)(values + row + ib * 64 + tc * 4);
            ky = *(const float4*)(keys   + row + jb * 64 + tc * 4);
            if (doSkk) kx = *(const float4*)(keys + row + ib * 64 + tc * 4);
        }

        if (doSkk) {
            #pragma unroll
            for (int tk = 0; tk < 16; ++tk) {
                float4 a1 = sGK[tk][ty];
                float4 a2 = sGV[tk][ty];
                float4 bb = sK [tk][tx];
                float av1[4] = {a1.x, a1.y, a1.z, a1.w};
                float av2[4] = {a2.x, a2.y, a2.z, a2.w};
                float bv [4] = {bb.x, bb.y, bb.z, bb.w};
                #pragma unroll
                for (int r = 0; r < 4; ++r)
                    #pragma unroll
                    for (int c = 0; c < 4; ++c) {
                        acc1[r][c] += av1[r] * bv[c];
                        acc2[r][c] += av2[r] * bv[c];
                    }
            }
        } else {
            #pragma unroll
            for (int tk = 0; tk < 16; ++tk) {
                float4 a2 = sGV[tk][ty];
                float4 bb = sK [tk][tx];
                float av2[4] = {a2.x, a2.y, a2.z, a2.w};
                float bv [4] = {bb.x, bb.y, bb.z, bb.w};
                #pragma unroll
                for (int r = 0; r < 4; ++r)
                    #pragma unroll
                    for (int c = 0; c < 4; ++c)
                        acc2[r][c] += av2[r] * bv[c];
            }
        }
        __syncthreads();
    }

    float* svk = g_Svk + (long)n * MATSZ;
    #pragma unroll
    for (int r = 0; r < 4; ++r) {
        const int x  = ib * 64 + ty * 4 + r;
        const int y0 = jb * 64 + tx * 4;
        *(float4*)(svk + (long)x * DD + y0) =
            make_float4(acc2[r][0], acc2[r][1], acc2[r][2], acc2[r][3]);
    }
    if (doSkk) {
        float* skk = g_Skk + (long)n * MATSZ;
        #pragma unroll
        for (int r = 0; r < 4; ++r) {
            const int x  = ib * 64 + ty * 4 + r;
            const int y0 = jb * 64 + tx * 4;
            *(float4*)(skk + (long)x * DD + y0) =
                make_float4(acc1[r][0], acc1[r][1], acc1[r][2], acc1[r][3]);
        }
        if (ib < jb) {
            #pragma unroll
            for (int r = 0; r < 4; ++r)
                #pragma unroll
                for (int c = 0; c < 4; ++c) {
                    const int x = ib * 64 + ty * 4 + r;
                    const int y = jb * 64 + tx * 4 + c;
                    skk[(long)y * DD + x] = acc1[r][c];
                }
        }
    }
}

// ---------------------------------------------------------------------------
// Phase A: per-chunk local scan + prefix products (R5 conflict-free layout).
//   M rows:  m <- a*m - m@Skk + svk_row   (zero init)
//   P rows:  p <- a*p - p@Skk             (identity init)
// Last window additionally writes the (P,S) chunk summary to tree buffer 0
// (fused kT_init). grid = (64 row-groups, CH chunks), block = 256.
// ---------------------------------------------------------------------------
__global__ __launch_bounds__(256) void kA_local(const float* __restrict__ alpha_p)
{
    __shared__ float srow[8][DD];   // rows 0-3: M, rows 4-7: P
    const int j  = threadIdx.x;
    const int c  = blockIdx.y;
    const int o0 = blockIdx.x * 4;
    const float a = 1.f / (1.f + expf(-alpha_p[0]));

    #pragma unroll
    for (int r = 0; r < 4; ++r) {
        srow[r][j] = 0.f;
        srow[4 + r][j] = (j == o0 + r) ? 1.f : 0.f;
    }
    __syncthreads();

    for (int s = 0; s < CS; ++s) {
        const int n = c * CS + s;
        const float* skk = g_Skk + (long)n * MATSZ;
        const float* svk = g_Svk + (long)n * MATSZ;

        const float sv0 = svk[(long)(o0 + 0) * DD + j];
        const float sv1 = svk[(long)(o0 + 1) * DD + j];
        const float sv2 = svk[(long)(o0 + 2) * DD + j];
        const float sv3 = svk[(long)(o0 + 3) * DD + j];

        u64 accM[4] = {0, 0, 0, 0};
        u64 accP[4] = {0, 0, 0, 0};

        float sb[16];
        #pragma unroll
        for (int u = 0; u < 16; ++u) sb[u] = skk[(long)u * DD + j];

        #pragma unroll
        for (int blk = 0; blk < 16; ++blk) {
            float sn[16];
            if (blk < 15) {
                const float* p = skk + (long)(blk + 1) * 16 * DD + j;
                #pragma unroll
                for (int u = 0; u < 16; ++u) sn[u] = p[(long)u * DD];
            } else {
                #pragma unroll
                for (int u = 0; u < 16; ++u) sn[u] = 0.f;
            }
            u64 sp[8];
            #pragma unroll
            for (int p = 0; p < 8; ++p) sp[p] = pack2f(sb[2 * p], sb[2 * p + 1]);

            const int db = blk * 16;
            #pragma unroll
            for (int r = 0; r < 4; ++r) {
                const u64* mrow = (const u64*)&srow[r][db];
                #pragma unroll
                for (int p = 0; p < 8; ++p) ffma2(accM[r], mrow[p], sp[p]);
            }
            #pragma unroll
            for (int r = 0; r < 4; ++r) {
                const u64* prow = (const u64*)&srow[4 + r][db];
                #pragma unroll
                for (int p = 0; p < 8; ++p) ffma2(accP[r], prow[p], sp[p]);
            }
            #pragma unroll
            for (int u = 0; u < 16; ++u) sb[u] = sn[u];
        }

        float nM[4], nP[4];
        const float svv[4] = {sv0, sv1, sv2, sv3};
        #pragma unroll
        for (int r = 0; r < 4; ++r) {
            nM[r] = a * srow[r][j] - hsum2(accM[r]) + svv[r];
            nP[r] = a * srow[4 + r][j] - hsum2(accP[r]);
        }
        __syncthreads();
        float* ms = g_Ms + (long)n * MATSZ;
        float* pp = g_P  + (long)n * MATSZ;
        #pragma unroll
        for (int r = 0; r < 4; ++r) {
            srow[r][j] = nM[r];
            srow[4 + r][j] = nP[r];
            ms[(long)(o0 + r) * DD + j] = nM[r];
            pp[(long)(o0 + r) * DD + j] = nP[r];
        }
        if (s == CS - 1) {   // fused kT_init: chunk summary into tree buffer 0
            float* ts = g_TS0 + (long)c * MATSZ;
            float* tp = g_TP0 + (long)c * MATSZ;
            #pragma unroll
            for (int r = 0; r < 4; ++r) {
                ts[(long)(o0 + r) * DD + j] = nM[r];
                tp[(long)(o0 + r) * DD + j] = nP[r];
            }
        }
        __syncthreads();
    }
}

// ---------------------------------------------------------------------------
// Tree level: Kogge-Stone inclusive scan over (P,S) with
//   combine(first,second) = (P1@P2, S1@P2 + S2).
// For chunk c >= stride: dst_c = combine(src_{c-stride}, src_c); else copy.
// onlyS=1 on the last level (P result unused there).
// grid = (16 tiles, CH, 2 or 1), block = 256.
// ---------------------------------------------------------------------------
__global__ __launch_bounds__(256) void kT_combine(int stride, int srcIdx, int onlyS)
{
    const float* srcP = srcIdx ? g_TP1 : g_TP0;
    const float* srcS = srcIdx ? g_TS1 : g_TS0;
    float*       dstP = srcIdx ? g_TP0 : g_TP1;
    float*       dstS = srcIdx ? g_TS0 : g_TS1;

    const int c   = blockIdx.y;
    const int isS = onlyS ? 1 : blockIdx.z;
    const int ib  = blockIdx.x >> 2;
    const int jb  = blockIdx.x & 3;
    const int tid = threadIdx.x;

    const float* srcM = isS ? srcS : srcP;
    float*       dstM = isS ? dstS : dstP;

    if (c < stride) {   // pass-through copy of this 64x64 tile
        const int lr = tid >> 2;
        const int lc = tid & 3;
        const long base = (long)c * MATSZ;
        #pragma unroll
        for (int it = 0; it < 4; ++it) {
            const long off = base + (long)(ib * 64 + lr) * DD + jb * 64 + (lc + it * 4) * 4;
            *(float4*)(dstM + off) = *(const float4*)(srcM + off);
        }
        return;
    }

    __shared__ float sA[16][68];
    __shared__ float sB[16][68];

    const int lr = tid >> 2;
    const int lc = tid & 3;
    const int pr = tid >> 4;
    const int pc = tid & 15;
    const int tx = tid & 15;
    const int ty = tid >> 4;

    const float* A  = srcM + (long)(c - stride) * MATSZ;   // S_{c-s} or P_{c-s}
    const float* Bm = srcP + (long)c * MATSZ;              // P_c
    float*       Dm = dstM + (long)c * MATSZ;

    float acc[4][4];
    #pragma unroll
    for (int r = 0; r < 4; ++r)
        #pragma unroll
        for (int q = 0; q < 4; ++q) acc[r][q] = 0.f;

    const long arow = (long)(ib * 64 + lr) * DD;

    float4 av = *(const float4*)(A + arow + lc * 4);
    float4 bv = *(const float4*)(Bm + (long)pr * DD + jb * 64 + pc * 4);

    for (int ch = 0; ch < 16; ++ch) {
        sA[lc * 4 + 0][lr] = av.x; sA[lc * 4 + 1][lr] = av.y;
        sA[lc * 4 + 2][lr] = av.z; sA[lc * 4 + 3][lr] = av.w;
        sB[pr][pc * 4 + 0] = bv.x; sB[pr][pc * 4 + 1] = bv.y;
        sB[pr][pc * 4 + 2] = bv.z; sB[pr][pc * 4 + 3] = bv.w;
        __syncthreads();

        if (ch < 15) {
            av = *(const float4*)(A + arow + (ch + 1) * 16 + lc * 4);
            bv = *(const float4*)(Bm + (long)((ch + 1) * 16 + pr) * DD + jb * 64 + pc * 4);
        }

        #pragma unroll
        for (int dk = 0; dk < 16; ++dk) {
            float aw[4], bw[4];
            #pragma unroll
            for (int r = 0; r < 4; ++r) aw[r] = sA[dk][ty * 4 + r];
            #pragma unroll
            for (int q = 0; q < 4; ++q) bw[q] = sB[dk][tx * 4 + q];
            #pragma unroll
            for (int r = 0; r < 4; ++r)
                #pragma unroll
                for (int q = 0; q < 4; ++q) acc[r][q] += aw[r] * bw[q];
        }
        __syncthreads();
    }

    const float* C0 = srcS + (long)c * MATSZ;
    #pragma unroll
    for (int r = 0; r < 4; ++r) {
        const long off = (long)(ib * 64 + ty * 4 + r) * DD + jb * 64 + tx * 4;
        float4 res = make_float4(acc[r][0], acc[r][1], acc[r][2], acc[r][3]);
        if (isS) {
            float4 cc = *(const float4*)(C0 + off);
            res.x += cc.x; res.y += cc.y; res.z += cc.z; res.w += cc.w;
        }
        *(float4*)(Dm + off) = res;
    }
}

// ---------------------------------------------------------------------------
// Phase C: fix-up GEMMs (parallel): Ms[n] += E_{c-1} @ P_n for chunks 1..CH-1.
// E = final tree buffer (g_TS0). grid = (16 tiles, NW - CS), block = 256.
// ---------------------------------------------------------------------------
__global__ __launch_bounds__(256) void kC_fix()
{
    __shared__ float sE[16][68];
    __shared__ float sP[16][68];

    const int nw  = blockIdx.y + CS;
    const int c   = nw / CS;
    const int ib  = blockIdx.x >> 2;
    const int jb  = blockIdx.x & 3;
    const int tid = threadIdx.x;
    const int lr  = tid >> 2;
    const int lc  = tid & 3;
    const int pr  = tid >> 4;
    const int pc  = tid & 15;
    const int tx  = tid & 15;
    const int ty  = tid >> 4;

    const float* E = g_TS0 + (long)(c - 1) * MATSZ;
    const float* P = g_P + (long)nw * MATSZ;
    float*      Ms = g_Ms + (long)nw * MATSZ;

    float acc[4][4];
    #pragma unroll
    for (int r = 0; r < 4; ++r)
        #pragma unroll
        for (int q = 0; q < 4; ++q) acc[r][q] = 0.f;

    const long erow = (long)(ib * 64 + lr) * DD;

    float4 ev = *(const float4*)(E + erow + lc * 4);
    float4 pv = *(const float4*)(P + (long)pr * DD + jb * 64 + pc * 4);

    for (int ch = 0; ch < 16; ++ch) {
        sE[lc * 4 + 0][lr] = ev.x; sE[lc * 4 + 1][lr] = ev.y;
        sE[lc * 4 + 2][lr] = ev.z; sE[lc * 4 + 3][lr] = ev.w;
        sP[pr][pc * 4 + 0] = pv.x; sP[pr][pc * 4 + 1] = pv.y;
        sP[pr][pc * 4 + 2] = pv.z; sP[pr][pc * 4 + 3] = pv.w;
        __syncthreads();

        if (ch < 15) {
            ev = *(const float4*)(E + erow + (ch + 1) * 16 + lc * 4);
            pv = *(const float4*)(P + (long)((ch + 1) * 16 + pr) * DD + jb * 64 + pc * 4);
        }

        #pragma unroll
        for (int dk = 0; dk < 16; ++dk) {
            float aw[4], bw[4];
            #pragma unroll
            for (int r = 0; r < 4; ++r) aw[r] = sE[dk][ty * 4 + r];
            #pragma unroll
            for (int q = 0; q < 4; ++q) bw[q] = sP[dk][tx * 4 + q];
            #pragma unroll
            for (int r = 0; r < 4; ++r)
                #pragma unroll
                for (int q = 0; q < 4; ++q) acc[r][q] += aw[r] * bw[q];
        }
        __syncthreads();
    }

    #pragma unroll
    for (int r = 0; r < 4; ++r) {
        float* dst = Ms + (long)(ib * 64 + ty * 4 + r) * DD + jb * 64 + tx * 4;
        float4 old = *(const float4*)dst;
        *(float4*)dst = make_float4(old.x + acc[r][0], old.y + acc[r][1],
                                    old.z + acc[r][2], old.w + acc[r][3]);
    }
}

// ---------------------------------------------------------------------------
// K3: retrieval. out[t][o] = sum_d q[t][d] * Ms[n][o][d]
// ---------------------------------------------------------------------------
__global__ __launch_bounds__(256) void k3_out(
    const float* __restrict__ queries, float* __restrict__ out)
{
    __shared__ float sQ[16][68];
    __shared__ float sM[16][68];

    const int n   = blockIdx.y;
    const int tb  = blockIdx.x >> 2;
    const int ob  = blockIdx.x & 3;
    const int tid = threadIdx.x;
    const int lr  = tid >> 2;
    const int lc  = tid & 3;
    const int tx  = tid & 15;
    const int ty  = tid >> 4;

    const float* Ms = g_Ms + (long)n * MATSZ;

    float acc[4][4];
    #pragma unroll
    for (int r = 0; r < 4; ++r)
        #pragma unroll
        for (int c = 0; c < 4; ++c) acc[r][c] = 0.f;

    const int t_ld = tb * 64 + lr;
    const int b_ld = t_ld >> 6;
    const int w_ld = t_ld & 63;
    const long qrow = ((long)b_ld * LL + (long)n * WW + w_ld) * DD;
    const long mrow = (long)(ob * 64 + lr) * DD;

    float4 qv = *(const float4*)(queries + qrow + lc * 4);
    float4 mv = *(const float4*)(Ms + mrow + lc * 4);

    for (int ch = 0; ch < 16; ++ch) {
        sQ[lc * 4 + 0][lr] = qv.x; sQ[lc * 4 + 1][lr] = qv.y;
        sQ[lc * 4 + 2][lr] = qv.z; sQ[lc * 4 + 3][lr] = qv.w;
        sM[lc * 4 + 0][lr] = mv.x; sM[lc * 4 + 1][lr] = mv.y;
        sM[lc * 4 + 2][lr] = mv.z; sM[lc * 4 + 3][lr] = mv.w;
        __syncthreads();

        if (ch < 15) {
            qv = *(const float4*)(queries + qrow + (ch + 1) * 16 + lc * 4);
            mv = *(const float4*)(Ms + mrow + (ch + 1) * 16 + lc * 4);
        }

        #pragma unroll
        for (int dk = 0; dk < 16; ++dk) {
            float aw[4], bw[4];
            #pragma unroll
            for (int r = 0; r < 4; ++r) aw[r] = sQ[dk][ty * 4 + r];
            #pragma unroll
            for (int c = 0; c < 4; ++c) bw[c] = sM[dk][tx * 4 + c];
            #pragma unroll
            for (int r = 0; r < 4; ++r)
                #pragma unroll
                for (int c = 0; c < 4; ++c) acc[r][c] += aw[r] * bw[c];
        }
        __syncthreads();
    }

    #pragma unroll
    for (int r = 0; r < 4; ++r) {
        const int t = tb * 64 + ty * 4 + r;
        const int b = t >> 6;
        const int w = t & 63;
        const long addr = ((long)b * LL + (long)n * WW + w) * DD + ob * 64 + tx * 4;
        *(float4*)(out + addr) = make_float4(acc[r][0], acc[r][1], acc[r][2], acc[r][3]);
    }
}

// ---------------------------------------------------------------------------
extern "C" void kernel_launch(void* const* d_in, const int* in_sizes, int n_in,
                              void* d_out, int out_size)
{
    const float* keys    = (const float*)d_in[0];
    const float* values  = (const float*)d_in[1];
    const float* queries = (const float*)d_in[2];
    const float* gammas  = (const float*)d_in[3];
    const float* alpha   = (const float*)d_in[4];
    float* out = (float*)d_out;

    k1_moments<<<dim3(16, NW), 256>>>(keys, values, gammas);
    kA_local<<<dim3(64, CH), 256>>>(alpha);
    kT_combine<<<dim3(16, CH, 2), 256>>>(1, 0, 0);  // buf0 -> buf1
    kT_combine<<<dim3(16, CH, 2), 256>>>(2, 1, 0);  // buf1 -> buf0
    kT_combine<<<dim3(16, CH, 2), 256>>>(4, 0, 0);  // buf0 -> buf1
    kT_combine<<<dim3(16, CH, 1), 256>>>(8, 1, 1);  // buf1 -> buf0, S only
    kC_fix<<<dim3(16, NW - CS), 256>>>();
    k3_out<<<dim3(32, NW), 256>>>(queries, out);
}

// round 12
// speedup vs baseline: 1.3268x; 1.0270x over previous
#include <cuda_runtime.h>
#include <math.h>

// OmegaRule: B=8, L=8192, D=256, W=64 -> NW=128 windows, T=B*W=512 rows/window.
#define BB 8
#define LL 8192
#define DD 256
#define WW 64
#define NW 128
#define TT 512
#define CH 16    // chunks
#define CS 8     // windows per chunk (CH*CS == NW)
#define MATSZ (DD * DD)

// Scratch (device globals; no allocation allowed).
__device__ float g_Skk[NW * MATSZ];
__device__ float g_Svk[NW * MATSZ];
__device__ float g_Ms [NW * MATSZ];
__device__ float g_P  [NW * MATSZ];
__device__ float g_TP0[CH * MATSZ];
__device__ float g_TP1[CH * MATSZ];
__device__ float g_TS0[CH * MATSZ];
__device__ float g_TS1[CH * MATSZ];

typedef unsigned long long u64;
__device__ __forceinline__ void ffma2(u64& acc, u64 a, u64 b) {
    asm("fma.rn.f32x2 %0, %1, %2, %0;" : "+l"(acc) : "l"(a), "l"(b));
}
__device__ __forceinline__ u64 pack2f(float x, float y) {
    u64 r; asm("mov.b64 %0, {%1, %2};" : "=l"(r) : "f"(x), "f"(y)); return r;
}
__device__ __forceinline__ void unpack2f(u64 v, float& x, float& y) {
    asm("mov.b64 {%0, %1}, %2;" : "=f"(x), "=f"(y) : "l"(v));
}
__device__ __forceinline__ float hsum2(u64 v) {
    float x, y; unpack2f(v, x, y); return x + y;
}

// ---------------------------------------------------------------------------
// K1: per-window moment matrices. Double-buffered smem, 1 sync/iteration.
//   Skk[n] = sum_t g_t k_t k_t^T   (computed for ib<=jb, mirrored)
//   Svk[n] = sum_t g_t v_t k_t^T   (all 16 tiles)
// ---------------------------------------------------------------------------
__global__ __launch_bounds__(256) void k1_moments(
    const float* __restrict__ keys,
    const float* __restrict__ values,
    const float* __restrict__ gammas)
{
    __shared__ float4 sGK[2][16][16];
    __shared__ float4 sGV[2][16][16];
    __shared__ float4 sK [2][16][16];

    const int n   = blockIdx.y;
    const int ib  = blockIdx.x >> 2;
    const int jb  = blockIdx.x & 3;
    const bool doSkk = (ib <= jb);
    const int tid = threadIdx.x;
    const int tr  = tid >> 4;
    const int tc  = tid & 15;
    const int tx  = tid & 15;
    const int ty  = tid >> 4;

    float acc1[4][4], acc2[4][4];
    #pragma unroll
    for (int r = 0; r < 4; ++r)
        #pragma unroll
        for (int c = 0; c < 4; ++c) { acc1[r][c] = 0.f; acc2[r][c] = 0.f; }

    float g; float4 kx, vx, ky;
    {
        const int t = tr;
        const int b = t >> 6;
        const int w = t & 63;
        const long row = ((long)b * LL + (long)n * WW + w) * DD;
        g  = __ldg(&gammas[(long)b * LL + (long)n * WW + w]);
        vx = *(const float4*)(values + row + ib * 64 + tc * 4);
        ky = *(const float4*)(keys   + row + jb * 64 + tc * 4);
        kx = *(const float4*)(keys   + row + ib * 64 + tc * 4);
    }
    // stage chunk 0 into buffer 0
    sGV[0][tr][tc] = make_float4(g * vx.x, g * vx.y, g * vx.z, g * vx.w);
    sK [0][tr][tc] = ky;
    if (doSkk)
        sGK[0][tr][tc] = make_float4(g * kx.x, g * kx.y, g * kx.z, g * kx.w);
    __syncthreads();

    for (int ch = 0; ch < TT / 16; ++ch) {
        const int cur = ch & 1;
        if (ch < TT / 16 - 1) {
            const int t = (ch + 1) * 16 + tr;
            const int b = t >> 6;
            const int w = t & 63;
            const long row = ((long)b * LL + (long)n * WW + w) * DD;
            g  = __ldg(&gammas[(long)b * LL + (long)n * WW + w]);
            vx = *(const float4*)(values + row + ib * 64 + tc * 4);
            ky = *(const float4*)(keys   + row + jb * 64 + tc * 4);
            if (doSkk) kx = *(const float4*)(keys + row + ib * 64 + tc * 4);
        }

        if (doSkk) {
            #pragma unroll
            for (int tk = 0; tk < 16; ++tk) {
                float4 a1 = sGK[cur][tk][ty];
                float4 a2 = sGV[cur][tk][ty];
                float4 bb = sK [cur][tk][tx];
                float av1[4] = {a1.x, a1.y, a1.z, a1.w};
                float av2[4] = {a2.x, a2.y, a2.z, a2.w};
                float bv [4] = {bb.x, bb.y, bb.z, bb.w};
                #pragma unroll
                for (int r = 0; r < 4; ++r)
                    #pragma unroll
                    for (int c = 0; c < 4; ++c) {
                        acc1[r][c] += av1[r] * bv[c];
                        acc2[r][c] += av2[r] * bv[c];
                    }
            }
        } else {
            #pragma unroll
            for (int tk = 0; tk < 16; ++tk) {
                float4 a2 = sGV[cur][tk][ty];
                float4 bb = sK [cur][tk][tx];
                float av2[4] = {a2.x, a2.y, a2.z, a2.w};
                float bv [4] = {bb.x, bb.y, bb.z, bb.w};
                #pragma unroll
                for (int r = 0; r < 4; ++r)
                    #pragma unroll
                    for (int c = 0; c < 4; ++c)
                        acc2[r][c] += av2[r] * bv[c];
            }
        }

        if (ch < TT / 16 - 1) {
            const int nxt = cur ^ 1;
            sGV[nxt][tr][tc] = make_float4(g * vx.x, g * vx.y, g * vx.z, g * vx.w);
            sK [nxt][tr][tc] = ky;
            if (doSkk)
                sGK[nxt][tr][tc] = make_float4(g * kx.x, g * kx.y, g * kx.z, g * kx.w);
            __syncthreads();
        }
    }

    float* svk = g_Svk + (long)n * MATSZ;
    #pragma unroll
    for (int r = 0; r < 4; ++r) {
        const int x  = ib * 64 + ty * 4 + r;
        const int y0 = jb * 64 + tx * 4;
        *(float4*)(svk + (long)x * DD + y0) =
            make_float4(acc2[r][0], acc2[r][1], acc2[r][2], acc2[r][3]);
    }
    if (doSkk) {
        float* skk = g_Skk + (long)n * MATSZ;
        #pragma unroll
        for (int r = 0; r < 4; ++r) {
            const int x  = ib * 64 + ty * 4 + r;
            const int y0 = jb * 64 + tx * 4;
            *(float4*)(skk + (long)x * DD + y0) =
                make_float4(acc1[r][0], acc1[r][1], acc1[r][2], acc1[r][3]);
        }
        if (ib < jb) {
            #pragma unroll
            for (int r = 0; r < 4; ++r)
                #pragma unroll
                for (int c = 0; c < 4; ++c) {
                    const int x = ib * 64 + ty * 4 + r;
                    const int y = jb * 64 + tx * 4 + c;
                    skk[(long)y * DD + x] = acc1[r][c];
                }
        }
    }
}

// ---------------------------------------------------------------------------
// Phase A: per-chunk local scan + prefix products (exact R5 version).
// grid = (64 row-groups, CH chunks), block = 256. Thread j owns column j.
// ---------------------------------------------------------------------------
__global__ __launch_bounds__(256) void kA_local(const float* __restrict__ alpha_p)
{
    __shared__ float srow[8][DD];   // rows 0-3: M, rows 4-7: P
    const int j  = threadIdx.x;
    const int c  = blockIdx.y;
    const int o0 = blockIdx.x * 4;
    const float a = 1.f / (1.f + expf(-alpha_p[0]));

    #pragma unroll
    for (int r = 0; r < 4; ++r) {
        srow[r][j] = 0.f;
        srow[4 + r][j] = (j == o0 + r) ? 1.f : 0.f;
    }
    __syncthreads();

    for (int s = 0; s < CS; ++s) {
        const int n = c * CS + s;
        const float* skk = g_Skk + (long)n * MATSZ;
        const float* svk = g_Svk + (long)n * MATSZ;

        const float sv0 = svk[(long)(o0 + 0) * DD + j];
        const float sv1 = svk[(long)(o0 + 1) * DD + j];
        const float sv2 = svk[(long)(o0 + 2) * DD + j];
        const float sv3 = svk[(long)(o0 + 3) * DD + j];

        u64 accM[4] = {0, 0, 0, 0};
        u64 accP[4] = {0, 0, 0, 0};

        float sb[16];
        #pragma unroll
        for (int u = 0; u < 16; ++u) sb[u] = skk[(long)u * DD + j];

        #pragma unroll
        for (int blk = 0; blk < 16; ++blk) {
            float sn[16];
            if (blk < 15) {
                const float* p = skk + (long)(blk + 1) * 16 * DD + j;
                #pragma unroll
                for (int u = 0; u < 16; ++u) sn[u] = p[(long)u * DD];
            } else {
                #pragma unroll
                for (int u = 0; u < 16; ++u) sn[u] = 0.f;
            }
            u64 sp[8];
            #pragma unroll
            for (int p = 0; p < 8; ++p) sp[p] = pack2f(sb[2 * p], sb[2 * p + 1]);

            const int db = blk * 16;
            #pragma unroll
            for (int r = 0; r < 4; ++r) {
                const u64* mrow = (const u64*)&srow[r][db];
                #pragma unroll
                for (int p = 0; p < 8; ++p) ffma2(accM[r], mrow[p], sp[p]);
            }
            #pragma unroll
            for (int r = 0; r < 4; ++r) {
                const u64* prow = (const u64*)&srow[4 + r][db];
                #pragma unroll
                for (int p = 0; p < 8; ++p) ffma2(accP[r], prow[p], sp[p]);
            }
            #pragma unroll
            for (int u = 0; u < 16; ++u) sb[u] = sn[u];
        }

        float nM[4], nP[4];
        const float svv[4] = {sv0, sv1, sv2, sv3};
        #pragma unroll
        for (int r = 0; r < 4; ++r) {
            nM[r] = a * srow[r][j] - hsum2(accM[r]) + svv[r];
            nP[r] = a * srow[4 + r][j] - hsum2(accP[r]);
        }
        __syncthreads();
        float* ms = g_Ms + (long)n * MATSZ;
        float* pp = g_P  + (long)n * MATSZ;
        #pragma unroll
        for (int r = 0; r < 4; ++r) {
            srow[r][j] = nM[r];
            srow[4 + r][j] = nP[r];
            ms[(long)(o0 + r) * DD + j] = nM[r];
            pp[(long)(o0 + r) * DD + j] = nP[r];
        }
        __syncthreads();
    }
}

// ---------------------------------------------------------------------------
// Tree init: gather chunk-end summaries into ping-pong buffer 0 (R5 version).
// ---------------------------------------------------------------------------
__global__ __launch_bounds__(256) void kT_init()
{
    const int j  = threadIdx.x;
    const int c  = blockIdx.y;
    const int o0 = blockIdx.x * 4;
    const long src = (long)(c * CS + CS - 1) * MATSZ;
    const long dst = (long)c * MATSZ;
    #pragma unroll
    for (int r = 0; r < 4; ++r) {
        const long off = (long)(o0 + r) * DD + j;
        g_TP0[dst + off] = g_P [src + off];
        g_TS0[dst + off] = g_Ms[src + off];
    }
}

// ---------------------------------------------------------------------------
// Tree level: Kogge-Stone inclusive scan over (P,S):
//   combine(first,second) = (P1@P2, S1@P2 + S2)
// Double-buffered smem, 1 sync/iteration.
// grid = (16 tiles, CH, 2), block = 256.
// ---------------------------------------------------------------------------
__global__ __launch_bounds__(256) void kT_combine(int stride, int srcIdx)
{
    const float* srcP = srcIdx ? g_TP1 : g_TP0;
    const float* srcS = srcIdx ? g_TS1 : g_TS0;
    float*       dstP = srcIdx ? g_TP0 : g_TP1;
    float*       dstS = srcIdx ? g_TS0 : g_TS1;

    const int c   = blockIdx.y;
    const int isS = blockIdx.z;
    const int ib  = blockIdx.x >> 2;
    const int jb  = blockIdx.x & 3;
    const int tid = threadIdx.x;

    const float* srcM = isS ? srcS : srcP;
    float*       dstM = isS ? dstS : dstP;

    if (c < stride) {   // pass-through copy
        const int lr = tid >> 2;
        const int lc = tid & 3;
        const long base = (long)c * MATSZ;
        #pragma unroll
        for (int it = 0; it < 4; ++it) {
            const long off = base + (long)(ib * 64 + lr) * DD + jb * 64 + (lc + it * 4) * 4;
            *(float4*)(dstM + off) = *(const float4*)(srcM + off);
        }
        return;
    }

    __shared__ float sA[2][16][68];
    __shared__ float sB[2][16][68];

    const int lr = tid >> 2;
    const int lc = tid & 3;
    const int pr = tid >> 4;
    const int pc = tid & 15;
    const int tx = tid & 15;
    const int ty = tid >> 4;

    const float* A  = srcM + (long)(c - stride) * MATSZ;
    const float* Bm = srcP + (long)c * MATSZ;
    float*       Dm = dstM + (long)c * MATSZ;

    float acc[4][4];
    #pragma unroll
    for (int r = 0; r < 4; ++r)
        #pragma unroll
        for (int q = 0; q < 4; ++q) acc[r][q] = 0.f;

    const long arow = (long)(ib * 64 + lr) * DD;

    float4 av = *(const float4*)(A + arow + lc * 4);
    float4 bv = *(const float4*)(Bm + (long)pr * DD + jb * 64 + pc * 4);
    sA[0][lc * 4 + 0][lr] = av.x; sA[0][lc * 4 + 1][lr] = av.y;
    sA[0][lc * 4 + 2][lr] = av.z; sA[0][lc * 4 + 3][lr] = av.w;
    sB[0][pr][pc * 4 + 0] = bv.x; sB[0][pr][pc * 4 + 1] = bv.y;
    sB[0][pr][pc * 4 + 2] = bv.z; sB[0][pr][pc * 4 + 3] = bv.w;
    __syncthreads();

    for (int ch = 0; ch < 16; ++ch) {
        const int cur = ch & 1;
        if (ch < 15) {
            av = *(const float4*)(A + arow + (ch + 1) * 16 + lc * 4);
            bv = *(const float4*)(Bm + (long)((ch + 1) * 16 + pr) * DD + jb * 64 + pc * 4);
        }

        #pragma unroll
        for (int dk = 0; dk < 16; ++dk) {
            float aw[4], bw[4];
            #pragma unroll
            for (int r = 0; r < 4; ++r) aw[r] = sA[cur][dk][ty * 4 + r];
            #pragma unroll
            for (int q = 0; q < 4; ++q) bw[q] = sB[cur][dk][tx * 4 + q];
            #pragma unroll
            for (int r = 0; r < 4; ++r)
                #pragma unroll
                for (int q = 0; q < 4; ++q) acc[r][q] += aw[r] * bw[q];
        }

        if (ch < 15) {
            const int nxt = cur ^ 1;
            sA[nxt][lc * 4 + 0][lr] = av.x; sA[nxt][lc * 4 + 1][lr] = av.y;
            sA[nxt][lc * 4 + 2][lr] = av.z; sA[nxt][lc * 4 + 3][lr] = av.w;
            sB[nxt][pr][pc * 4 + 0] = bv.x; sB[nxt][pr][pc * 4 + 1] = bv.y;
            sB[nxt][pr][pc * 4 + 2] = bv.z; sB[nxt][pr][pc * 4 + 3] = bv.w;
            __syncthreads();
        }
    }

    const float* C0 = srcS + (long)c * MATSZ;
    #pragma unroll
    for (int r = 0; r < 4; ++r) {
        const long off = (long)(ib * 64 + ty * 4 + r) * DD + jb * 64 + tx * 4;
        float4 res = make_float4(acc[r][0], acc[r][1], acc[r][2], acc[r][3]);
        if (isS) {
            float4 cc = *(const float4*)(C0 + off);
            res.x += cc.x; res.y += cc.y; res.z += cc.z; res.w += cc.w;
        }
        *(float4*)(Dm + off) = res;
    }
}

// ---------------------------------------------------------------------------
// Phase C: fix-up GEMMs: Ms[n] += E_{c-1} @ P_n for chunks 1..CH-1.
// Double-buffered smem, 1 sync/iteration. E = g_TS0.
// ---------------------------------------------------------------------------
__global__ __launch_bounds__(256) void kC_fix()
{
    __shared__ float sE[2][16][68];
    __shared__ float sP[2][16][68];

    const int nw  = blockIdx.y + CS;
    const int c   = nw / CS;
    const int ib  = blockIdx.x >> 2;
    const int jb  = blockIdx.x & 3;
    const int tid = threadIdx.x;
    const int lr  = tid >> 2;
    const int lc  = tid & 3;
    const int pr  = tid >> 4;
    const int pc  = tid & 15;
    const int tx  = tid & 15;
    const int ty  = tid >> 4;

    const float* E = g_TS0 + (long)(c - 1) * MATSZ;
    const float* P = g_P + (long)nw * MATSZ;
    float*      Ms = g_Ms + (long)nw * MATSZ;

    float acc[4][4];
    #pragma unroll
    for (int r = 0; r < 4; ++r)
        #pragma unroll
        for (int q = 0; q < 4; ++q) acc[r][q] = 0.f;

    const long erow = (long)(ib * 64 + lr) * DD;

    float4 ev = *(const float4*)(E + erow + lc * 4);
    float4 pv = *(const float4*)(P + (long)pr * DD + jb * 64 + pc * 4);
    sE[0][lc * 4 + 0][lr] = ev.x; sE[0][lc * 4 + 1][lr] = ev.y;
    sE[0][lc * 4 + 2][lr] = ev.z; sE[0][lc * 4 + 3][lr] = ev.w;
    sP[0][pr][pc * 4 + 0] = pv.x; sP[0][pr][pc * 4 + 1] = pv.y;
    sP[0][pr][pc * 4 + 2] = pv.z; sP[0][pr][pc * 4 + 3] = pv.w;
    __syncthreads();

    for (int ch = 0; ch < 16; ++ch) {
        const int cur = ch & 1;
        if (ch < 15) {
            ev = *(const float4*)(E + erow + (ch + 1) * 16 + lc * 4);
            pv = *(const float4*)(P + (long)((ch + 1) * 16 + pr) * DD + jb * 64 + pc * 4);
        }

        #pragma unroll
        for (int dk = 0; dk < 16; ++dk) {
            float aw[4], bw[4];
            #pragma unroll
            for (int r = 0; r < 4; ++r) aw[r] = sE[cur][dk][ty * 4 + r];
            #pragma unroll
            for (int q = 0; q < 4; ++q) bw[q] = sP[cur][dk][tx * 4 + q];
            #pragma unroll
            for (int r = 0; r < 4; ++r)
                #pragma unroll
                for (int q = 0; q < 4; ++q) acc[r][q] += aw[r] * bw[q];
        }

        if (ch < 15) {
            const int nxt = cur ^ 1;
            sE[nxt][lc * 4 + 0][lr] = ev.x; sE[nxt][lc * 4 + 1][lr] = ev.y;
            sE[nxt][lc * 4 + 2][lr] = ev.z; sE[nxt][lc * 4 + 3][lr] = ev.w;
            sP[nxt][pr][pc * 4 + 0] = pv.x; sP[nxt][pr][pc * 4 + 1] = pv.y;
            sP[nxt][pr][pc * 4 + 2] = pv.z; sP[nxt][pr][pc * 4 + 3] = pv.w;
            __syncthreads();
        }
    }

    #pragma unroll
    for (int r = 0; r < 4; ++r) {
        float* dst = Ms + (long)(ib * 64 + ty * 4 + r) * DD + jb * 64 + tx * 4;
        float4 old = *(const float4*)dst;
        *(float4*)dst = make_float4(old.x + acc[r][0], old.y + acc[r][1],
                                    old.z + acc[r][2], old.w + acc[r][3]);
    }
}

// ---------------------------------------------------------------------------
// K3: retrieval. out[t][o] = sum_d q[t][d] * Ms[n][o][d]
// Double-buffered smem, 1 sync/iteration.
// ---------------------------------------------------------------------------
__global__ __launch_bounds__(256) void k3_out(
    const float* __restrict__ queries, float* __restrict__ out)
{
    __shared__ float sQ[2][16][68];
    __shared__ float sM[2][16][68];

    const int n   = blockIdx.y;
    const int tb  = blockIdx.x >> 2;
    const int ob  = blockIdx.x & 3;
    const int tid = threadIdx.x;
    const int lr  = tid >> 2;
    const int lc  = tid & 3;
    const int tx  = tid & 15;
    const int ty  = tid >> 4;

    const float* Ms = g_Ms + (long)n * MATSZ;

    float acc[4][4];
    #pragma unroll
    for (int r = 0; r < 4; ++r)
        #pragma unroll
        for (int c = 0; c < 4; ++c) acc[r][c] = 0.f;

    const int t_ld = tb * 64 + lr;
    const int b_ld = t_ld >> 6;
    const int w_ld = t_ld & 63;
    const long qrow = ((long)b_ld * LL + (long)n * WW + w_ld) * DD;
    const long mrow = (long)(ob * 64 + lr) * DD;

    float4 qv = *(const float4*)(queries + qrow + lc * 4);
    float4 mv = *(const float4*)(Ms + mrow + lc * 4);
    sQ[0][lc * 4 + 0][lr] = qv.x; sQ[0][lc * 4 + 1][lr] = qv.y;
    sQ[0][lc * 4 + 2][lr] = qv.z; sQ[0][lc * 4 + 3][lr] = qv.w;
    sM[0][lc * 4 + 0][lr] = mv.x; sM[0][lc * 4 + 1][lr] = mv.y;
    sM[0][lc * 4 + 2][lr] = mv.z; sM[0][lc * 4 + 3][lr] = mv.w;
    __syncthreads();

    for (int ch = 0; ch < 16; ++ch) {
        const int cur = ch & 1;
        if (ch < 15) {
            qv = *(const float4*)(queries + qrow + (ch + 1) * 16 + lc * 4);
            mv = *(const float4*)(Ms + mrow + (ch + 1) * 16 + lc * 4);
        }

        #pragma unroll
        for (int dk = 0; dk < 16; ++dk) {
            float aw[4], bw[4];
            #pragma unroll
            for (int r = 0; r < 4; ++r) aw[r] = sQ[cur][dk][ty * 4 + r];
            #pragma unroll
            for (int c = 0; c < 4; ++c) bw[c] = sM[cur][dk][tx * 4 + c];
            #pragma unroll
            for (int r = 0; r < 4; ++r)
                #pragma unroll
                for (int c = 0; c < 4; ++c) acc[r][c] += aw[r] * bw[c];
        }

        if (ch < 15) {
            const int nxt = cur ^ 1;
            sQ[nxt][lc * 4 + 0][lr] = qv.x; sQ[nxt][lc * 4 + 1][lr] = qv.y;
            sQ[nxt][lc * 4 + 2][lr] = qv.z; sQ[nxt][lc * 4 + 3][lr] = qv.w;
            sM[nxt][lc * 4 + 0][lr] = mv.x; sM[nxt][lc * 4 + 1][lr] = mv.y;
            sM[nxt][lc * 4 + 2][lr] = mv.z; sM[nxt][lc * 4 + 3][lr] = mv.w;
            __syncthreads();
        }
    }

    #pragma unroll
    for (int r = 0; r < 4; ++r) {
        const int t = tb * 64 + ty * 4 + r;
        const int b = t >> 6;
        const int w = t & 63;
        const long addr = ((long)b * LL + (long)n * WW + w) * DD + ob * 64 + tx * 4;
        *(float4*)(out + addr) = make_float4(acc[r][0], acc[r][1], acc[r][2], acc[r][3]);
    }
}

// ---------------------------------------------------------------------------
extern "C" void kernel_launch(void* const* d_in, const int* in_sizes, int n_in,
                              void* d_out, int out_size)
{
    const float* keys    = (const float*)d_in[0];
    const float* values  = (const float*)d_in[1];
    const float* queries = (const float*)d_in[2];
    const float* gammas  = (const float*)d_in[3];
    const float* alpha   = (const float*)d_in[4];
    float* out = (float*)d_out;

    k1_moments<<<dim3(16, NW), 256>>>(keys, values, gammas);
    kA_local<<<dim3(64, CH), 256>>>(alpha);
    kT_init<<<dim3(64, CH), 256>>>();
    kT_combine<<<dim3(16, CH, 2), 256>>>(1, 0);  // buf0 -> buf1
    kT_combine<<<dim3(16, CH, 2), 256>>>(2, 1);  // buf1 -> buf0
    kT_combine<<<dim3(16, CH, 2), 256>>>(4, 0);  // buf0 -> buf1
    kT_combine<<<dim3(16, CH, 2), 256>>>(8, 1);  // buf1 -> buf0 (final: g_TS0)
    kC_fix<<<dim3(16, NW - CS), 256>>>();
    k3_out<<<dim3(32, NW), 256>>>(queries, out);
}

// round 13
// speedup vs baseline: 1.3659x; 1.0295x over previous
#include <cuda_runtime.h>
#include <cuda_bf16.h>
#include <math.h>

// OmegaRule: B=8, L=8192, D=256, W=64 -> NW=128 windows, T=B*W=512 rows/window.
#define BB 8
#define LL 8192
#define DD 256
#define WW 64
#define NW 128
#define TT 512
#define CH 16    // chunks
#define CS 8     // windows per chunk (CH*CS == NW)
#define MATSZ (DD * DD)

// Scratch (device globals; no allocation allowed).
__device__ float g_Skk[NW * MATSZ];
__device__ float g_Svk[NW * MATSZ];
__device__ float g_Ms [NW * MATSZ];
__device__ float g_P  [NW * MATSZ];
__device__ float g_TP0[CH * MATSZ];
__device__ float g_TP1[CH * MATSZ];
__device__ float g_TS0[CH * MATSZ];
__device__ float g_TS1[CH * MATSZ];

typedef unsigned long long u64;
__device__ __forceinline__ void ffma2(u64& acc, u64 a, u64 b) {
    asm("fma.rn.f32x2 %0, %1, %2, %0;" : "+l"(acc) : "l"(a), "l"(b));
}
__device__ __forceinline__ u64 pack2f(float x, float y) {
    u64 r; asm("mov.b64 %0, {%1, %2};" : "=l"(r) : "f"(x), "f"(y)); return r;
}
__device__ __forceinline__ void unpack2f(u64 v, float& x, float& y) {
    asm("mov.b64 {%0, %1}, %2;" : "=f"(x), "=f"(y) : "l"(v));
}
__device__ __forceinline__ float hsum2(u64 v) {
    float x, y; unpack2f(v, x, y); return x + y;
}

// bf16 pair pack: low half = x (even k), high half = y (odd k).
__device__ __forceinline__ unsigned pack_bf16(float x, float y) {
    __nv_bfloat162 h = __floats2bfloat162_rn(x, y);
    return *(unsigned*)&h;
}

// m16n8k16 bf16 MMA, fp32 accumulate (row.col).
__device__ __forceinline__ void mma_bf16(float* c, const unsigned* a, const unsigned* b) {
    asm volatile(
        "mma.sync.aligned.m16n8k16.row.col.f32.bf16.bf16.f32 "
        "{%0,%1,%2,%3}, {%4,%5,%6,%7}, {%8,%9}, {%0,%1,%2,%3};"
        : "+f"(c[0]), "+f"(c[1]), "+f"(c[2]), "+f"(c[3])
        : "r"(a[0]), "r"(a[1]), "r"(a[2]), "r"(a[3]), "r"(b[0]), "r"(b[1]));
}

// ---------------------------------------------------------------------------
// K1: per-window moment matrices (R5 version: symmetry + register prefetch).
// ---------------------------------------------------------------------------
__global__ __launch_bounds__(256) void k1_moments(
    const float* __restrict__ keys,
    const float* __restrict__ values,
    const float* __restrict__ gammas)
{
    __shared__ float4 sGK[16][16];
    __shared__ float4 sGV[16][16];
    __shared__ float4 sK [16][16];

    const int n   = blockIdx.y;
    const int ib  = blockIdx.x >> 2;
    const int jb  = blockIdx.x & 3;
    const bool doSkk = (ib <= jb);
    const int tid = threadIdx.x;
    const int tr  = tid >> 4;
    const int tc  = tid & 15;
    const int tx  = tid & 15;
    const int ty  = tid >> 4;

    float acc1[4][4], acc2[4][4];
    #pragma unroll
    for (int r = 0; r < 4; ++r)
        #pragma unroll
        for (int c = 0; c < 4; ++c) { acc1[r][c] = 0.f; acc2[r][c] = 0.f; }

    float g; float4 kx, vx, ky;
    {
        const int t = tr;
        const int b = t >> 6;
        const int w = t & 63;
        const long row = ((long)b * LL + (long)n * WW + w) * DD;
        g  = __ldg(&gammas[(long)b * LL + (long)n * WW + w]);
        vx = *(const float4*)(values + row + ib * 64 + tc * 4);
        ky = *(const float4*)(keys   + row + jb * 64 + tc * 4);
        kx = *(const float4*)(keys   + row + ib * 64 + tc * 4);
    }

    for (int ch = 0; ch < TT / 16; ++ch) {
        sGV[tr][tc] = make_float4(g * vx.x, g * vx.y, g * vx.z, g * vx.w);
        sK [tr][tc] = ky;
        if (doSkk)
            sGK[tr][tc] = make_float4(g * kx.x, g * kx.y, g * kx.z, g * kx.w);
        __syncthreads();

        if (ch < TT / 16 - 1) {
            const int t = (ch + 1) * 16 + tr;
            const int b = t >> 6;
            const int w = t & 63;
            const long row = ((long)b * LL + (long)n * WW + w) * DD;
            g  = __ldg(&gammas[(long)b * LL + (long)n * WW + w]);
            vx = *(const float4*)(values + row + ib * 64 + tc * 4);
            ky = *(const float4*)(keys   + row + jb * 64 + tc * 4);
            if (doSkk) kx = *(const float4*)(keys + row + ib * 64 + tc * 4);
        }

        if (doSkk) {
            #pragma unroll
            for (int tk = 0; tk < 16; ++tk) {
                float4 a1 = sGK[tk][ty];
                float4 a2 = sGV[tk][ty];
                float4 bb = sK [tk][tx];
                float av1[4] = {a1.x, a1.y, a1.z, a1.w};
                float av2[4] = {a2.x, a2.y, a2.z, a2.w};
                float bv [4] = {bb.x, bb.y, bb.z, bb.w};
                #pragma unroll
                for (int r = 0; r < 4; ++r)
                    #pragma unroll
                    for (int c = 0; c < 4; ++c) {
                        acc1[r][c] += av1[r] * bv[c];
                        acc2[r][c] += av2[r] * bv[c];
                    }
            }
        } else {
            #pragma unroll
            for (int tk = 0; tk < 16; ++tk) {
                float4 a2 = sGV[tk][ty];
                float4 bb = sK [tk][tx];
                float av2[4] = {a2.x, a2.y, a2.z, a2.w};
                float bv [4] = {bb.x, bb.y, bb.z, bb.w};
                #pragma unroll
                for (int r = 0; r < 4; ++r)
                    #pragma unroll
                    for (int c = 0; c < 4; ++c)
                        acc2[r][c] += av2[r] * bv[c];
            }
        }
        __syncthreads();
    }

    float* svk = g_Svk + (long)n * MATSZ;
    #pragma unroll
    for (int r = 0; r < 4; ++r) {
        const int x  = ib * 64 + ty * 4 + r;
        const int y0 = jb * 64 + tx * 4;
        *(float4*)(svk + (long)x * DD + y0) =
            make_float4(acc2[r][0], acc2[r][1], acc2[r][2], acc2[r][3]);
    }
    if (doSkk) {
        float* skk = g_Skk + (long)n * MATSZ;
        #pragma unroll
        for (int r = 0; r < 4; ++r) {
            const int x  = ib * 64 + ty * 4 + r;
            const int y0 = jb * 64 + tx * 4;
            *(float4*)(skk + (long)x * DD + y0) =
                make_float4(acc1[r][0], acc1[r][1], acc1[r][2], acc1[r][3]);
        }
        if (ib < jb) {
            #pragma unroll
            for (int r = 0; r < 4; ++r)
                #pragma unroll
                for (int c = 0; c < 4; ++c) {
                    const int x = ib * 64 + ty * 4 + r;
                    const int y = jb * 64 + tx * 4 + c;
                    skk[(long)y * DD + x] = acc1[r][c];
                }
        }
    }
}

// ---------------------------------------------------------------------------
// Phase A: per-chunk local scan + prefix products (exact R5 version).
// ---------------------------------------------------------------------------
__global__ __launch_bounds__(256) void kA_local(const float* __restrict__ alpha_p)
{
    __shared__ float srow[8][DD];
    const int j  = threadIdx.x;
    const int c  = blockIdx.y;
    const int o0 = blockIdx.x * 4;
    const float a = 1.f / (1.f + expf(-alpha_p[0]));

    #pragma unroll
    for (int r = 0; r < 4; ++r) {
        srow[r][j] = 0.f;
        srow[4 + r][j] = (j == o0 + r) ? 1.f : 0.f;
    }
    __syncthreads();

    for (int s = 0; s < CS; ++s) {
        const int n = c * CS + s;
        const float* skk = g_Skk + (long)n * MATSZ;
        const float* svk = g_Svk + (long)n * MATSZ;

        const float sv0 = svk[(long)(o0 + 0) * DD + j];
        const float sv1 = svk[(long)(o0 + 1) * DD + j];
        const float sv2 = svk[(long)(o0 + 2) * DD + j];
        const float sv3 = svk[(long)(o0 + 3) * DD + j];

        u64 accM[4] = {0, 0, 0, 0};
        u64 accP[4] = {0, 0, 0, 0};

        float sb[16];
        #pragma unroll
        for (int u = 0; u < 16; ++u) sb[u] = skk[(long)u * DD + j];

        #pragma unroll
        for (int blk = 0; blk < 16; ++blk) {
            float sn[16];
            if (blk < 15) {
                const float* p = skk + (long)(blk + 1) * 16 * DD + j;
                #pragma unroll
                for (int u = 0; u < 16; ++u) sn[u] = p[(long)u * DD];
            } else {
                #pragma unroll
                for (int u = 0; u < 16; ++u) sn[u] = 0.f;
            }
            u64 sp[8];
            #pragma unroll
            for (int p = 0; p < 8; ++p) sp[p] = pack2f(sb[2 * p], sb[2 * p + 1]);

            const int db = blk * 16;
            #pragma unroll
            for (int r = 0; r < 4; ++r) {
                const u64* mrow = (const u64*)&srow[r][db];
                #pragma unroll
                for (int p = 0; p < 8; ++p) ffma2(accM[r], mrow[p], sp[p]);
            }
            #pragma unroll
            for (int r = 0; r < 4; ++r) {
                const u64* prow = (const u64*)&srow[4 + r][db];
                #pragma unroll
                for (int p = 0; p < 8; ++p) ffma2(accP[r], prow[p], sp[p]);
            }
            #pragma unroll
            for (int u = 0; u < 16; ++u) sb[u] = sn[u];
        }

        float nM[4], nP[4];
        const float svv[4] = {sv0, sv1, sv2, sv3};
        #pragma unroll
        for (int r = 0; r < 4; ++r) {
            nM[r] = a * srow[r][j] - hsum2(accM[r]) + svv[r];
            nP[r] = a * srow[4 + r][j] - hsum2(accP[r]);
        }
        __syncthreads();
        float* ms = g_Ms + (long)n * MATSZ;
        float* pp = g_P  + (long)n * MATSZ;
        #pragma unroll
        for (int r = 0; r < 4; ++r) {
            srow[r][j] = nM[r];
            srow[4 + r][j] = nP[r];
            ms[(long)(o0 + r) * DD + j] = nM[r];
            pp[(long)(o0 + r) * DD + j] = nP[r];
        }
        __syncthreads();
    }
}

// ---------------------------------------------------------------------------
// Tree init (R5): gather chunk-end summaries into ping-pong buffer 0.
// ---------------------------------------------------------------------------
__global__ __launch_bounds__(256) void kT_init()
{
    const int j  = threadIdx.x;
    const int c  = blockIdx.y;
    const int o0 = blockIdx.x * 4;
    const long src = (long)(c * CS + CS - 1) * MATSZ;
    const long dst = (long)c * MATSZ;
    #pragma unroll
    for (int r = 0; r < 4; ++r) {
        const long off = (long)(o0 + r) * DD + j;
        g_TP0[dst + off] = g_P [src + off];
        g_TS0[dst + off] = g_Ms[src + off];
    }
}

// ---------------------------------------------------------------------------
// Tree level (exact R5): Kogge-Stone over (P,S).
// ---------------------------------------------------------------------------
__global__ __launch_bounds__(256) void kT_combine(int stride, int srcIdx)
{
    const float* srcP = srcIdx ? g_TP1 : g_TP0;
    const float* srcS = srcIdx ? g_TS1 : g_TS0;
    float*       dstP = srcIdx ? g_TP0 : g_TP1;
    float*       dstS = srcIdx ? g_TS0 : g_TS1;

    const int c   = blockIdx.y;
    const int isS = blockIdx.z;
    const int ib  = blockIdx.x >> 2;
    const int jb  = blockIdx.x & 3;
    const int tid = threadIdx.x;

    const float* srcM = isS ? srcS : srcP;
    float*       dstM = isS ? dstS : dstP;

    if (c < stride) {
        const int lr = tid >> 2;
        const int lc = tid & 3;
        const long base = (long)c * MATSZ;
        #pragma unroll
        for (int it = 0; it < 4; ++it) {
            const long off = base + (long)(ib * 64 + lr) * DD + jb * 64 + (lc + it * 4) * 4;
            *(float4*)(dstM + off) = *(const float4*)(srcM + off);
        }
        return;
    }

    __shared__ float sA[16][68];
    __shared__ float sB[16][68];

    const int lr = tid >> 2;
    const int lc = tid & 3;
    const int pr = tid >> 4;
    const int pc = tid & 15;
    const int tx = tid & 15;
    const int ty = tid >> 4;

    const float* A  = srcM + (long)(c - stride) * MATSZ;
    const float* Bm = srcP + (long)c * MATSZ;
    float*       Dm = dstM + (long)c * MATSZ;

    float acc[4][4];
    #pragma unroll
    for (int r = 0; r < 4; ++r)
        #pragma unroll
        for (int q = 0; q < 4; ++q) acc[r][q] = 0.f;

    const long arow = (long)(ib * 64 + lr) * DD;

    float4 av = *(const float4*)(A + arow + lc * 4);
    float4 bv = *(const float4*)(Bm + (long)pr * DD + jb * 64 + pc * 4);

    for (int ch = 0; ch < 16; ++ch) {
        sA[lc * 4 + 0][lr] = av.x; sA[lc * 4 + 1][lr] = av.y;
        sA[lc * 4 + 2][lr] = av.z; sA[lc * 4 + 3][lr] = av.w;
        sB[pr][pc * 4 + 0] = bv.x; sB[pr][pc * 4 + 1] = bv.y;
        sB[pr][pc * 4 + 2] = bv.z; sB[pr][pc * 4 + 3] = bv.w;
        __syncthreads();

        if (ch < 15) {
            av = *(const float4*)(A + arow + (ch + 1) * 16 + lc * 4);
            bv = *(const float4*)(Bm + (long)((ch + 1) * 16 + pr) * DD + jb * 64 + pc * 4);
        }

        #pragma unroll
        for (int dk = 0; dk < 16; ++dk) {
            float aw[4], bw[4];
            #pragma unroll
            for (int r = 0; r < 4; ++r) aw[r] = sA[dk][ty * 4 + r];
            #pragma unroll
            for (int q = 0; q < 4; ++q) bw[q] = sB[dk][tx * 4 + q];
            #pragma unroll
            for (int r = 0; r < 4; ++r)
                #pragma unroll
                for (int q = 0; q < 4; ++q) acc[r][q] += aw[r] * bw[q];
        }
        __syncthreads();
    }

    const float* C0 = srcS + (long)c * MATSZ;
    #pragma unroll
    for (int r = 0; r < 4; ++r) {
        const long off = (long)(ib * 64 + ty * 4 + r) * DD + jb * 64 + tx * 4;
        float4 res = make_float4(acc[r][0], acc[r][1], acc[r][2], acc[r][3]);
        if (isS) {
            float4 cc = *(const float4*)(C0 + off);
            res.x += cc.x; res.y += cc.y; res.z += cc.z; res.w += cc.w;
        }
        *(float4*)(Dm + off) = res;
    }
}

// ---------------------------------------------------------------------------
// Phase C (exact R5): Ms[n] += E_{c-1} @ P_n for chunks 1..CH-1.
// ---------------------------------------------------------------------------
__global__ __launch_bounds__(256) void kC_fix()
{
    __shared__ float sE[16][68];
    __shared__ float sP[16][68];

    const int nw  = blockIdx.y + CS;
    const int c   = nw / CS;
    const int ib  = blockIdx.x >> 2;
    const int jb  = blockIdx.x & 3;
    const int tid = threadIdx.x;
    const int lr  = tid >> 2;
    const int lc  = tid & 3;
    const int pr  = tid >> 4;
    const int pc  = tid & 15;
    const int tx  = tid & 15;
    const int ty  = tid >> 4;

    const float* E = g_TS0 + (long)(c - 1) * MATSZ;
    const float* P = g_P + (long)nw * MATSZ;
    float*      Ms = g_Ms + (long)nw * MATSZ;

    float acc[4][4];
    #pragma unroll
    for (int r = 0; r < 4; ++r)
        #pragma unroll
        for (int q = 0; q < 4; ++q) acc[r][q] = 0.f;

    const long erow = (long)(ib * 64 + lr) * DD;

    float4 ev = *(const float4*)(E + erow + lc * 4);
    float4 pv = *(const float4*)(P + (long)pr * DD + jb * 64 + pc * 4);

    for (int ch = 0; ch < 16; ++ch) {
        sE[lc * 4 + 0][lr] = ev.x; sE[lc * 4 + 1][lr] = ev.y;
        sE[lc * 4 + 2][lr] = ev.z; sE[lc * 4 + 3][lr] = ev.w;
        sP[pr][pc * 4 + 0] = pv.x; sP[pr][pc * 4 + 1] = pv.y;
        sP[pr][pc * 4 + 2] = pv.z; sP[pr][pc * 4 + 3] = pv.w;
        __syncthreads();

        if (ch < 15) {
            ev = *(const float4*)(E + erow + (ch + 1) * 16 + lc * 4);
            pv = *(const float4*)(P + (long)((ch + 1) * 16 + pr) * DD + jb * 64 + pc * 4);
        }

        #pragma unroll
        for (int dk = 0; dk < 16; ++dk) {
            float aw[4], bw[4];
            #pragma unroll
            for (int r = 0; r < 4; ++r) aw[r] = sE[dk][ty * 4 + r];
            #pragma unroll
            for (int q = 0; q < 4; ++q) bw[q] = sP[dk][tx * 4 + q];
            #pragma unroll
            for (int r = 0; r < 4; ++r)
                #pragma unroll
                for (int q = 0; q < 4; ++q) acc[r][q] += aw[r] * bw[q];
        }
        __syncthreads();
    }

    #pragma unroll
    for (int r = 0; r < 4; ++r) {
        float* dst = Ms + (long)(ib * 64 + ty * 4 + r) * DD + jb * 64 + tx * 4;
        float4 old = *(const float4*)dst;
        *(float4*)dst = make_float4(old.x + acc[r][0], old.y + acc[r][1],
                                    old.z + acc[r][2], old.w + acc[r][3]);
    }
}

// ---------------------------------------------------------------------------
// K3 (NEW): retrieval via bf16x3 split-precision tensor-core MMA.
// out[t][o] = sum_d q[t][d] * Ms[n][o][d]
// A = q (row-major t x d), B = Ms (row-major o x d == col-major d x o).
// x = hi + lo (bf16 each); x*y ~= hi*hi + hi*lo + lo*hi, fp32 accumulate.
// grid = (32 tiles, NW): tile = 64(t) x 64(o); 8 warps: 2(m) x 4(n);
// per warp 32x16; mma m16n8k16; K chunked 4 x 64.
// ---------------------------------------------------------------------------
__global__ __launch_bounds__(256) void k3_out(
    const float* __restrict__ queries, float* __restrict__ out)
{
    // word layout: row stride 36 words (32 data + 4 pad) -> conflict-free frags
    __shared__ unsigned sQh[64 * 36], sQl[64 * 36];
    __shared__ unsigned sMh[64 * 36], sMl[64 * 36];

    const int n   = blockIdx.y;
    const int tb  = blockIdx.x >> 2;   // t block (0..7)
    const int ob  = blockIdx.x & 3;    // o block (0..3)
    const int tid = threadIdx.x;
    const int wid = tid >> 5;
    const int lane = tid & 31;
    const int gq  = lane >> 2;         // groupID 0..7
    const int q4  = lane & 3;

    const int m0 = (wid >> 2) * 32;    // warp m-base (0 or 32)
    const int n0 = (wid & 3) * 16;     // warp n-base (0,16,32,48)

    // conversion role: row = tid>>2 (0..63), seg = tid&3 (16-col segment)
    const int crow = tid >> 2;
    const int cseg = tid & 3;

    const float* qsrc = queries + ((long)tb * LL + (long)n * WW + crow) * DD;
    const float* msrc = g_Ms + (long)n * MATSZ + (long)(ob * 64 + crow) * DD;

    float C[2][2][4];
    #pragma unroll
    for (int mi = 0; mi < 2; ++mi)
        #pragma unroll
        for (int ni = 0; ni < 2; ++ni)
            #pragma unroll
            for (int e = 0; e < 4; ++e) C[mi][ni][e] = 0.f;

    for (int chu = 0; chu < 4; ++chu) {
        // ---- stage & convert 64x64 chunk of q and M to hi/lo bf16 ----
        {
            const int colbase = cseg * 16;
            const int wbase = crow * 36 + (colbase >> 1);
            #pragma unroll
            for (int f = 0; f < 4; ++f) {
                float4 qv = *(const float4*)(qsrc + chu * 64 + colbase + f * 4);
                float4 mv = *(const float4*)(msrc + chu * 64 + colbase + f * 4);

                float qh[4] = {qv.x, qv.y, qv.z, qv.w};
                float mh[4] = {mv.x, mv.y, mv.z, mv.w};
                float ql[4], ml[4];
                float qhr[4], mhr[4];
                #pragma unroll
                for (int e = 0; e < 4; ++e) {
                    __nv_bfloat16 h = __float2bfloat16(qh[e]);
                    qhr[e] = __bfloat162float(h);
                    ql[e] = qh[e] - qhr[e];
                    __nv_bfloat16 h2 = __float2bfloat16(mh[e]);
                    mhr[e] = __bfloat162float(h2);
                    ml[e] = mh[e] - mhr[e];
                }
                sQh[wbase + f * 2 + 0] = pack_bf16(qhr[0], qhr[1]);
                sQh[wbase + f * 2 + 1] = pack_bf16(qhr[2], qhr[3]);
                sQl[wbase + f * 2 + 0] = pack_bf16(ql[0], ql[1]);
                sQl[wbase + f * 2 + 1] = pack_bf16(ql[2], ql[3]);
                sMh[wbase + f * 2 + 0] = pack_bf16(mhr[0], mhr[1]);
                sMh[wbase + f * 2 + 1] = pack_bf16(mhr[2], mhr[3]);
                sMl[wbase + f * 2 + 0] = pack_bf16(ml[0], ml[1]);
                sMl[wbase + f * 2 + 1] = pack_bf16(ml[2], ml[3]);
            }
        }
        __syncthreads();

        // ---- 4 k-steps of 16 over this chunk ----
        #pragma unroll
        for (int ks = 0; ks < 4; ++ks) {
            const int kw = ks * 8;   // word offset of k-step
            unsigned Ah[2][4], Al[2][4];
            #pragma unroll
            for (int mi = 0; mi < 2; ++mi) {
                const int r0 = (m0 + mi * 16 + gq) * 36 + kw + q4;
                const int r8 = (m0 + mi * 16 + gq + 8) * 36 + kw + q4;
                Ah[mi][0] = sQh[r0];     Ah[mi][1] = sQh[r8];
                Ah[mi][2] = sQh[r0 + 4]; Ah[mi][3] = sQh[r8 + 4];
                Al[mi][0] = sQl[r0];     Al[mi][1] = sQl[r8];
                Al[mi][2] = sQl[r0 + 4]; Al[mi][3] = sQl[r8 + 4];
            }
            unsigned Bh[2][2], Bl[2][2];
            #pragma unroll
            for (int ni = 0; ni < 2; ++ni) {
                const int rb = (n0 + ni * 8 + gq) * 36 + kw + q4;
                Bh[ni][0] = sMh[rb]; Bh[ni][1] = sMh[rb + 4];
                Bl[ni][0] = sMl[rb]; Bl[ni][1] = sMl[rb + 4];
            }
            #pragma unroll
            for (int mi = 0; mi < 2; ++mi)
                #pragma unroll
                for (int ni = 0; ni < 2; ++ni) {
                    mma_bf16(C[mi][ni], Ah[mi], Bh[ni]);
                    mma_bf16(C[mi][ni], Ah[mi], Bl[ni]);
                    mma_bf16(C[mi][ni], Al[mi], Bh[ni]);
                }
        }
        __syncthreads();
    }

    // ---- epilogue: write C fragments ----
    // c0,c1: row g, cols 2*(lane%4)+{0,1}; c2,c3: row g+8, same cols.
    #pragma unroll
    for (int mi = 0; mi < 2; ++mi) {
        #pragma unroll
        for (int ni = 0; ni < 2; ++ni) {
            const int ocol = ob * 64 + n0 + ni * 8 + q4 * 2;
            const int tl0 = m0 + mi * 16 + gq;
            const int tl8 = tl0 + 8;
            float* d0 = out + ((long)tb * LL + (long)n * WW + tl0) * DD + ocol;
            float* d8 = out + ((long)tb * LL + (long)n * WW + tl8) * DD + ocol;
            *(float2*)d0 = make_float2(C[mi][ni][0], C[mi][ni][1]);
            *(float2*)d8 = make_float2(C[mi][ni][2], C[mi][ni][3]);
        }
    }
}

// ---------------------------------------------------------------------------
extern "C" void kernel_launch(void* const* d_in, const int* in_sizes, int n_in,
                              void* d_out, int out_size)
{
    const float* keys    = (const float*)d_in[0];
    const float* values  = (const float*)d_in[1];
    const float* queries = (const float*)d_in[2];
    const float* gammas  = (const float*)d_in[3];
    const float* alpha   = (const float*)d_in[4];
    float* out = (float*)d_out;

    k1_moments<<<dim3(16, NW), 256>>>(keys, values, gammas);
    kA_local<<<dim3(64, CH), 256>>>(alpha);
    kT_init<<<dim3(64, CH), 256>>>();
    kT_combine<<<dim3(16, CH, 2), 256>>>(1, 0);  // buf0 -> buf1
    kT_combine<<<dim3(16, CH, 2), 256>>>(2, 1);  // buf1 -> buf0
    kT_combine<<<dim3(16, CH, 2), 256>>>(4, 0);  // buf0 -> buf1
    kT_combine<<<dim3(16, CH, 2), 256>>>(8, 1);  // buf1 -> buf0 (final: g_TS0)
    kC_fix<<<dim3(16, NW - CS), 256>>>();
    k3_out<<<dim3(32, NW), 256>>>(queries, out);
}

// round 14
// speedup vs baseline: 1.4651x; 1.0726x over previous
#include <cuda_runtime.h>
#include <cuda_bf16.h>
#include <math.h>

// OmegaRule: B=8, L=8192, D=256, W=64 -> NW=128 windows, T=B*W=512 rows/window.
#define BB 8
#define LL 8192
#define DD 256
#define WW 64
#define NW 128
#define TT 512
#define CH 16    // chunks
#define CS 8     // windows per chunk (CH*CS == NW)
#define MATSZ (DD * DD)
#define MATW (MATSZ / 2)   // matrix size in bf16-pair words

// Scratch (device globals; no allocation allowed).
__device__ float g_Skk[NW * MATSZ];
__device__ float g_Svk[NW * MATSZ];
__device__ float g_Ms [NW * MATSZ];
__device__ float g_P  [NW * MATSZ];
__device__ float g_TP0[CH * MATSZ];
__device__ float g_TP1[CH * MATSZ];
__device__ float g_TS0[CH * MATSZ];
__device__ float g_TS1[CH * MATSZ];
// bf16 hi/lo word-packed buffers (low half = even index)
__device__ __align__(16) unsigned g_Qh [BB * LL * DD / 2];
__device__ __align__(16) unsigned g_Ql [BB * LL * DD / 2];
__device__ __align__(16) unsigned g_Msh[NW * MATW];
__device__ __align__(16) unsigned g_Msl[NW * MATW];
__device__ __align__(16) unsigned g_PTh[NW * MATW];   // transposed P: PT[y][d]
__device__ __align__(16) unsigned g_PTl[NW * MATW];
__device__ __align__(16) unsigned g_Eh [CH * MATW];
__device__ __align__(16) unsigned g_El [CH * MATW];

typedef unsigned long long u64;
__device__ __forceinline__ void ffma2(u64& acc, u64 a, u64 b) {
    asm("fma.rn.f32x2 %0, %1, %2, %0;" : "+l"(acc) : "l"(a), "l"(b));
}
__device__ __forceinline__ u64 pack2f(float x, float y) {
    u64 r; asm("mov.b64 %0, {%1, %2};" : "=l"(r) : "f"(x), "f"(y)); return r;
}
__device__ __forceinline__ void unpack2f(u64 v, float& x, float& y) {
    asm("mov.b64 {%0, %1}, %2;" : "=f"(x), "=f"(y) : "l"(v));
}
__device__ __forceinline__ float hsum2(u64 v) {
    float x, y; unpack2f(v, x, y); return x + y;
}

// bf16 pair pack: low half = x (even index), high half = y (odd index).
__device__ __forceinline__ unsigned pack_bf16(float x, float y) {
    __nv_bfloat162 h = __floats2bfloat162_rn(x, y);
    return *(unsigned*)&h;
}
__device__ __forceinline__ float bf_hi_f(float x) {   // x rounded to bf16, back to f32
    return __bfloat162float(__float2bfloat16(x));
}

// m16n8k16 bf16 MMA, fp32 accumulate (row.col).
__device__ __forceinline__ void mma_bf16(float* c, const unsigned* a, const unsigned* b) {
    asm volatile(
        "mma.sync.aligned.m16n8k16.row.col.f32.bf16.bf16.f32 "
        "{%0,%1,%2,%3}, {%4,%5,%6,%7}, {%8,%9}, {%0,%1,%2,%3};"
        : "+f"(c[0]), "+f"(c[1]), "+f"(c[2]), "+f"(c[3])
        : "r"(a[0]), "r"(a[1]), "r"(a[2]), "r"(a[3]), "r"(b[0]), "r"(b[1]));
}

// ---------------------------------------------------------------------------
// Conversion kernels (bandwidth-bound).
// ---------------------------------------------------------------------------
__global__ __launch_bounds__(256) void kConvQ(const float* __restrict__ q)
{
    const long i = ((long)blockIdx.x * 256 + threadIdx.x) * 4;
    float4 v = *(const float4*)(q + i);
    float h0 = bf_hi_f(v.x), h1 = bf_hi_f(v.y), h2 = bf_hi_f(v.z), h3 = bf_hi_f(v.w);
    g_Qh[i / 2 + 0] = pack_bf16(v.x, v.y);
    g_Qh[i / 2 + 1] = pack_bf16(v.z, v.w);
    g_Ql[i / 2 + 0] = pack_bf16(v.x - h0, v.y - h1);
    g_Ql[i / 2 + 1] = pack_bf16(v.z - h2, v.w - h3);
}

__global__ __launch_bounds__(256) void kConvM()
{
    const long i = ((long)blockIdx.x * 256 + threadIdx.x) * 4;
    float4 v = *(const float4*)(g_Ms + i);
    float h0 = bf_hi_f(v.x), h1 = bf_hi_f(v.y), h2 = bf_hi_f(v.z), h3 = bf_hi_f(v.w);
    g_Msh[i / 2 + 0] = pack_bf16(v.x, v.y);
    g_Msh[i / 2 + 1] = pack_bf16(v.z, v.w);
    g_Msl[i / 2 + 0] = pack_bf16(v.x - h0, v.y - h1);
    g_Msl[i / 2 + 1] = pack_bf16(v.z - h2, v.w - h3);
}

__global__ __launch_bounds__(256) void kTrE()
{
    const long i = ((long)blockIdx.x * 256 + threadIdx.x) * 4;
    float4 v = *(const float4*)(g_TS0 + i);
    float h0 = bf_hi_f(v.x), h1 = bf_hi_f(v.y), h2 = bf_hi_f(v.z), h3 = bf_hi_f(v.w);
    g_Eh[i / 2 + 0] = pack_bf16(v.x, v.y);
    g_Eh[i / 2 + 1] = pack_bf16(v.z, v.w);
    g_El[i / 2 + 0] = pack_bf16(v.x - h0, v.y - h1);
    g_El[i / 2 + 1] = pack_bf16(v.z - h2, v.w - h3);
}

// Transpose+convert P (windows CS..NW-1): PT[y][d] = P[d][y], bf16 hi/lo.
// grid = (64 tiles of 32x32, NW - CS), block = (32, 8).
__global__ void kTrP()
{
    __shared__ float tile[32][33];
    const int n  = CS + blockIdx.y;
    const int dB = (blockIdx.x & 7) * 32;
    const int yB = (blockIdx.x >> 3) * 32;
    const int tx = threadIdx.x, ty = threadIdx.y;

    const float* P = g_P + (long)n * MATSZ;
    #pragma unroll
    for (int j = 0; j < 4; ++j)
        tile[ty + j * 8][tx] = P[(long)(dB + ty + j * 8) * DD + yB + tx];
    __syncthreads();

    if (tx < 16) {
        #pragma unroll
        for (int j = 0; j < 4; ++j) {
            const int yl = ty + j * 8;
            const float e0 = tile[2 * tx][yl];
            const float e1 = tile[2 * tx + 1][yl];
            const long w = (long)n * MATW + (long)(yB + yl) * (DD / 2) + dB / 2 + tx;
            g_PTh[w] = pack_bf16(e0, e1);
            g_PTl[w] = pack_bf16(e0 - bf_hi_f(e0), e1 - bf_hi_f(e1));
        }
    }
}

// ---------------------------------------------------------------------------
// K1: per-window moment matrices (R5 scalar version).
// ---------------------------------------------------------------------------
__global__ __launch_bounds__(256) void k1_moments(
    const float* __restrict__ keys,
    const float* __restrict__ values,
    const float* __restrict__ gammas)
{
    __shared__ float4 sGK[16][16];
    __shared__ float4 sGV[16][16];
    __shared__ float4 sK [16][16];

    const int n   = blockIdx.y;
    const int ib  = blockIdx.x >> 2;
    const int jb  = blockIdx.x & 3;
    const bool doSkk = (ib <= jb);
    const int tid = threadIdx.x;
    const int tr  = tid >> 4;
    const int tc  = tid & 15;
    const int tx  = tid & 15;
    const int ty  = tid >> 4;

    float acc1[4][4], acc2[4][4];
    #pragma unroll
    for (int r = 0; r < 4; ++r)
        #pragma unroll
        for (int c = 0; c < 4; ++c) { acc1[r][c] = 0.f; acc2[r][c] = 0.f; }

    float g; float4 kx, vx, ky;
    {
        const int t = tr;
        const int b = t >> 6;
        const int w = t & 63;
        const long row = ((long)b * LL + (long)n * WW + w) * DD;
        g  = __ldg(&gammas[(long)b * LL + (long)n * WW + w]);
        vx = *(const float4*)(values + row + ib * 64 + tc * 4);
        ky = *(const float4*)(keys   + row + jb * 64 + tc * 4);
        kx = *(const float4*)(keys   + row + ib * 64 + tc * 4);
    }

    for (int ch = 0; ch < TT / 16; ++ch) {
        sGV[tr][tc] = make_float4(g * vx.x, g * vx.y, g * vx.z, g * vx.w);
        sK [tr][tc] = ky;
        if (doSkk)
            sGK[tr][tc] = make_float4(g * kx.x, g * kx.y, g * kx.z, g * kx.w);
        __syncthreads();

        if (ch < TT / 16 - 1) {
            const int t = (ch + 1) * 16 + tr;
            const int b = t >> 6;
            const int w = t & 63;
            const long row = ((long)b * LL + (long)n * WW + w) * DD;
            g  = __ldg(&gammas[(long)b * LL + (long)n * WW + w]);
            vx = *(const float4*)(values + row + ib * 64 + tc * 4);
            ky = *(const float4*)(keys   + row + jb * 64 + tc * 4);
            if (doSkk) kx = *(const float4*)(keys + row + ib * 64 + tc * 4);
        }

        if (doSkk) {
            #pragma unroll
            for (int tk = 0; tk < 16; ++tk) {
                float4 a1 = sGK[tk][ty];
                float4 a2 = sGV[tk][ty];
                float4 bb = sK [tk][tx];
                float av1[4] = {a1.x, a1.y, a1.z, a1.w};
                float av2[4] = {a2.x, a2.y, a2.z, a2.w};
                float bv [4] = {bb.x, bb.y, bb.z, bb.w};
                #pragma unroll
                for (int r = 0; r < 4; ++r)
                    #pragma unroll
                    for (int c = 0; c < 4; ++c) {
                        acc1[r][c] += av1[r] * bv[c];
                        acc2[r][c] += av2[r] * bv[c];
                    }
            }
        } else {
            #pragma unroll
            for (int tk = 0; tk < 16; ++tk) {
                float4 a2 = sGV[tk][ty];
                float4 bb = sK [tk][tx];
                float av2[4] = {a2.x, a2.y, a2.z, a2.w};
                float bv [4] = {bb.x, bb.y, bb.z, bb.w};
                #pragma unroll
                for (int r = 0; r < 4; ++r)
                    #pragma unroll
                    for (int c = 0; c < 4; ++c)
                        acc2[r][c] += av2[r] * bv[c];
            }
        }
        __syncthreads();
    }

    float* svk = g_Svk + (long)n * MATSZ;
    #pragma unroll
    for (int r = 0; r < 4; ++r) {
        const int x  = ib * 64 + ty * 4 + r;
        const int y0 = jb * 64 + tx * 4;
        *(float4*)(svk + (long)x * DD + y0) =
            make_float4(acc2[r][0], acc2[r][1], acc2[r][2], acc2[r][3]);
    }
    if (doSkk) {
        float* skk = g_Skk + (long)n * MATSZ;
        #pragma unroll
        for (int r = 0; r < 4; ++r) {
            const int x  = ib * 64 + ty * 4 + r;
            const int y0 = jb * 64 + tx * 4;
            *(float4*)(skk + (long)x * DD + y0) =
                make_float4(acc1[r][0], acc1[r][1], acc1[r][2], acc1[r][3]);
        }
        if (ib < jb) {
            #pragma unroll
            for (int r = 0; r < 4; ++r)
                #pragma unroll
                for (int c = 0; c < 4; ++c) {
                    const int x = ib * 64 + ty * 4 + r;
                    const int y = jb * 64 + tx * 4 + c;
                    skk[(long)y * DD + x] = acc1[r][c];
                }
        }
    }
}

// ---------------------------------------------------------------------------
// Phase A: per-chunk local scan + prefix products (exact R5 version).
// ---------------------------------------------------------------------------
__global__ __launch_bounds__(256) void kA_local(const float* __restrict__ alpha_p)
{
    __shared__ float srow[8][DD];
    const int j  = threadIdx.x;
    const int c  = blockIdx.y;
    const int o0 = blockIdx.x * 4;
    const float a = 1.f / (1.f + expf(-alpha_p[0]));

    #pragma unroll
    for (int r = 0; r < 4; ++r) {
        srow[r][j] = 0.f;
        srow[4 + r][j] = (j == o0 + r) ? 1.f : 0.f;
    }
    __syncthreads();

    for (int s = 0; s < CS; ++s) {
        const int n = c * CS + s;
        const float* skk = g_Skk + (long)n * MATSZ;
        const float* svk = g_Svk + (long)n * MATSZ;

        const float sv0 = svk[(long)(o0 + 0) * DD + j];
        const float sv1 = svk[(long)(o0 + 1) * DD + j];
        const float sv2 = svk[(long)(o0 + 2) * DD + j];
        const float sv3 = svk[(long)(o0 + 3) * DD + j];

        u64 accM[4] = {0, 0, 0, 0};
        u64 accP[4] = {0, 0, 0, 0};

        float sb[16];
        #pragma unroll
        for (int u = 0; u < 16; ++u) sb[u] = skk[(long)u * DD + j];

        #pragma unroll
        for (int blk = 0; blk < 16; ++blk) {
            float sn[16];
            if (blk < 15) {
                const float* p = skk + (long)(blk + 1) * 16 * DD + j;
                #pragma unroll
                for (int u = 0; u < 16; ++u) sn[u] = p[(long)u * DD];
            } else {
                #pragma unroll
                for (int u = 0; u < 16; ++u) sn[u] = 0.f;
            }
            u64 sp[8];
            #pragma unroll
            for (int p = 0; p < 8; ++p) sp[p] = pack2f(sb[2 * p], sb[2 * p + 1]);

            const int db = blk * 16;
            #pragma unroll
            for (int r = 0; r < 4; ++r) {
                const u64* mrow = (const u64*)&srow[r][db];
                #pragma unroll
                for (int p = 0; p < 8; ++p) ffma2(accM[r], mrow[p], sp[p]);
            }
            #pragma unroll
            for (int r = 0; r < 4; ++r) {
                const u64* prow = (const u64*)&srow[4 + r][db];
                #pragma unroll
                for (int p = 0; p < 8; ++p) ffma2(accP[r], prow[p], sp[p]);
            }
            #pragma unroll
            for (int u = 0; u < 16; ++u) sb[u] = sn[u];
        }

        float nM[4], nP[4];
        const float svv[4] = {sv0, sv1, sv2, sv3};
        #pragma unroll
        for (int r = 0; r < 4; ++r) {
            nM[r] = a * srow[r][j] - hsum2(accM[r]) + svv[r];
            nP[r] = a * srow[4 + r][j] - hsum2(accP[r]);
        }
        __syncthreads();
        float* ms = g_Ms + (long)n * MATSZ;
        float* pp = g_P  + (long)n * MATSZ;
        #pragma unroll
        for (int r = 0; r < 4; ++r) {
            srow[r][j] = nM[r];
            srow[4 + r][j] = nP[r];
            ms[(long)(o0 + r) * DD + j] = nM[r];
            pp[(long)(o0 + r) * DD + j] = nP[r];
        }
        __syncthreads();
    }
}

// ---------------------------------------------------------------------------
// Tree init (R5): gather chunk-end summaries into ping-pong buffer 0.
// ---------------------------------------------------------------------------
__global__ __launch_bounds__(256) void kT_init()
{
    const int j  = threadIdx.x;
    const int c  = blockIdx.y;
    const int o0 = blockIdx.x * 4;
    const long src = (long)(c * CS + CS - 1) * MATSZ;
    const long dst = (long)c * MATSZ;
    #pragma unroll
    for (int r = 0; r < 4; ++r) {
        const long off = (long)(o0 + r) * DD + j;
        g_TP0[dst + off] = g_P [src + off];
        g_TS0[dst + off] = g_Ms[src + off];
    }
}

// ---------------------------------------------------------------------------
// Tree level (exact R5 scalar): Kogge-Stone over (P,S).
// ---------------------------------------------------------------------------
__global__ __launch_bounds__(256) void kT_combine(int stride, int srcIdx)
{
    const float* srcP = srcIdx ? g_TP1 : g_TP0;
    const float* srcS = srcIdx ? g_TS1 : g_TS0;
    float*       dstP = srcIdx ? g_TP0 : g_TP1;
    float*       dstS = srcIdx ? g_TS0 : g_TS1;

    const int c   = blockIdx.y;
    const int isS = blockIdx.z;
    const int ib  = blockIdx.x >> 2;
    const int jb  = blockIdx.x & 3;
    const int tid = threadIdx.x;

    const float* srcM = isS ? srcS : srcP;
    float*       dstM = isS ? dstS : dstP;

    if (c < stride) {
        const int lr = tid >> 2;
        const int lc = tid & 3;
        const long base = (long)c * MATSZ;
        #pragma unroll
        for (int it = 0; it < 4; ++it) {
            const long off = base + (long)(ib * 64 + lr) * DD + jb * 64 + (lc + it * 4) * 4;
            *(float4*)(dstM + off) = *(const float4*)(srcM + off);
        }
        return;
    }

    __shared__ float sA[16][68];
    __shared__ float sB[16][68];

    const int lr = tid >> 2;
    const int lc = tid & 3;
    const int pr = tid >> 4;
    const int pc = tid & 15;
    const int tx = tid & 15;
    const int ty = tid >> 4;

    const float* A  = srcM + (long)(c - stride) * MATSZ;
    const float* Bm = srcP + (long)c * MATSZ;
    float*       Dm = dstM + (long)c * MATSZ;

    float acc[4][4];
    #pragma unroll
    for (int r = 0; r < 4; ++r)
        #pragma unroll
        for (int q = 0; q < 4; ++q) acc[r][q] = 0.f;

    const long arow = (long)(ib * 64 + lr) * DD;

    float4 av = *(const float4*)(A + arow + lc * 4);
    float4 bv = *(const float4*)(Bm + (long)pr * DD + jb * 64 + pc * 4);

    for (int ch = 0; ch < 16; ++ch) {
        sA[lc * 4 + 0][lr] = av.x; sA[lc * 4 + 1][lr] = av.y;
        sA[lc * 4 + 2][lr] = av.z; sA[lc * 4 + 3][lr] = av.w;
        sB[pr][pc * 4 + 0] = bv.x; sB[pr][pc * 4 + 1] = bv.y;
        sB[pr][pc * 4 + 2] = bv.z; sB[pr][pc * 4 + 3] = bv.w;
        __syncthreads();

        if (ch < 15) {
            av = *(const float4*)(A + arow + (ch + 1) * 16 + lc * 4);
            bv = *(const float4*)(Bm + (long)((ch + 1) * 16 + pr) * DD + jb * 64 + pc * 4);
        }

        #pragma unroll
        for (int dk = 0; dk < 16; ++dk) {
            float aw[4], bw[4];
            #pragma unroll
            for (int r = 0; r < 4; ++r) aw[r] = sA[dk][ty * 4 + r];
            #pragma unroll
            for (int q = 0; q < 4; ++q) bw[q] = sB[dk][tx * 4 + q];
            #pragma unroll
            for (int r = 0; r < 4; ++r)
                #pragma unroll
                for (int q = 0; q < 4; ++q) acc[r][q] += aw[r] * bw[q];
        }
        __syncthreads();
    }

    const float* C0 = srcS + (long)c * MATSZ;
    #pragma unroll
    for (int r = 0; r < 4; ++r) {
        const long off = (long)(ib * 64 + ty * 4 + r) * DD + jb * 64 + tx * 4;
        float4 res = make_float4(acc[r][0], acc[r][1], acc[r][2], acc[r][3]);
        if (isS) {
            float4 cc = *(const float4*)(C0 + off);
            res.x += cc.x; res.y += cc.y; res.z += cc.z; res.w += cc.w;
        }
        *(float4*)(Dm + off) = res;
    }
}

// ---------------------------------------------------------------------------
// Phase C (NEW): Ms[n] += E_{c-1} @ P_n via bf16x3 tensor-core MMA.
// A = E[x][d] (pre-converted bf16 row-major), B = PT[y][d] (pre-converted,
// transposed). Same tile/fragment scheme as k3 (validated R13).
// grid = (32 tile-pairs? no: 16 tiles, NW - CS), block = 256.
// ---------------------------------------------------------------------------
__global__ __launch_bounds__(256) void kC_fix()
{
    __shared__ unsigned sAh[64 * 36], sAl[64 * 36];
    __shared__ unsigned sBh[64 * 36], sBl[64 * 36];

    const int nw  = blockIdx.y + CS;
    const int c   = nw / CS;
    const int ib  = blockIdx.x >> 2;
    const int jb  = blockIdx.x & 3;
    const int tid = threadIdx.x;
    const int wid = tid >> 5;
    const int lane = tid & 31;
    const int gq  = lane >> 2;
    const int q4  = lane & 3;

    const int m0 = (wid >> 2) * 32;
    const int n0 = (wid & 3) * 16;

    const int crow = tid >> 2;
    const int cseg = tid & 3;

    // word bases (row-major words, 128 per row)
    const long aw0 = (long)(c - 1) * MATW + (long)(ib * 64 + crow) * (DD / 2) + cseg * 8;
    const long bw0 = (long)nw * MATW + (long)(jb * 64 + crow) * (DD / 2) + cseg * 8;

    float C[2][2][4];
    #pragma unroll
    for (int mi = 0; mi < 2; ++mi)
        #pragma unroll
        for (int ni = 0; ni < 2; ++ni)
            #pragma unroll
            for (int e = 0; e < 4; ++e) C[mi][ni][e] = 0.f;

    for (int chu = 0; chu < 4; ++chu) {
        const int wbase = crow * 36 + cseg * 8;
        {
            uint4 a0 = *(const uint4*)(g_Eh + aw0 + chu * 32);
            uint4 a1 = *(const uint4*)(g_Eh + aw0 + chu * 32 + 4);
            uint4 l0 = *(const uint4*)(g_El + aw0 + chu * 32);
            uint4 l1 = *(const uint4*)(g_El + aw0 + chu * 32 + 4);
            sAh[wbase + 0] = a0.x; sAh[wbase + 1] = a0.y; sAh[wbase + 2] = a0.z; sAh[wbase + 3] = a0.w;
            sAh[wbase + 4] = a1.x; sAh[wbase + 5] = a1.y; sAh[wbase + 6] = a1.z; sAh[wbase + 7] = a1.w;
            sAl[wbase + 0] = l0.x; sAl[wbase + 1] = l0.y; sAl[wbase + 2] = l0.z; sAl[wbase + 3] = l0.w;
            sAl[wbase + 4] = l1.x; sAl[wbase + 5] = l1.y; sAl[wbase + 6] = l1.z; sAl[wbase + 7] = l1.w;
            uint4 b0 = *(const uint4*)(g_PTh + bw0 + chu * 32);
            uint4 b1 = *(const uint4*)(g_PTh + bw0 + chu * 32 + 4);
            uint4 m0v = *(const uint4*)(g_PTl + bw0 + chu * 32);
            uint4 m1v = *(const uint4*)(g_PTl + bw0 + chu * 32 + 4);
            sBh[wbase + 0] = b0.x; sBh[wbase + 1] = b0.y; sBh[wbase + 2] = b0.z; sBh[wbase + 3] = b0.w;
            sBh[wbase + 4] = b1.x; sBh[wbase + 5] = b1.y; sBh[wbase + 6] = b1.z; sBh[wbase + 7] = b1.w;
            sBl[wbase + 0] = m0v.x; sBl[wbase + 1] = m0v.y; sBl[wbase + 2] = m0v.z; sBl[wbase + 3] = m0v.w;
            sBl[wbase + 4] = m1v.x; sBl[wbase + 5] = m1v.y; sBl[wbase + 6] = m1v.z; sBl[wbase + 7] = m1v.w;
        }
        __syncthreads();

        #pragma unroll
        for (int ks = 0; ks < 4; ++ks) {
            const int kw = ks * 8;
            unsigned Ah[2][4], Al[2][4];
            #pragma unroll
            for (int mi = 0; mi < 2; ++mi) {
                const int r0 = (m0 + mi * 16 + gq) * 36 + kw + q4;
                const int r8 = (m0 + mi * 16 + gq + 8) * 36 + kw + q4;
                Ah[mi][0] = sAh[r0];     Ah[mi][1] = sAh[r8];
                Ah[mi][2] = sAh[r0 + 4]; Ah[mi][3] = sAh[r8 + 4];
                Al[mi][0] = sAl[r0];     Al[mi][1] = sAl[r8];
                Al[mi][2] = sAl[r0 + 4]; Al[mi][3] = sAl[r8 + 4];
            }
            unsigned Bh[2][2], Bl[2][2];
            #pragma unroll
            for (int ni = 0; ni < 2; ++ni) {
                const int rb = (n0 + ni * 8 + gq) * 36 + kw + q4;
                Bh[ni][0] = sBh[rb]; Bh[ni][1] = sBh[rb + 4];
                Bl[ni][0] = sBl[rb]; Bl[ni][1] = sBl[rb + 4];
            }
            #pragma unroll
            for (int mi = 0; mi < 2; ++mi)
                #pragma unroll
                for (int ni = 0; ni < 2; ++ni) {
                    mma_bf16(C[mi][ni], Ah[mi], Bh[ni]);
                    mma_bf16(C[mi][ni], Ah[mi], Bl[ni]);
                    mma_bf16(C[mi][ni], Al[mi], Bh[ni]);
                }
        }
        __syncthreads();
    }

    float* Ms = g_Ms + (long)nw * MATSZ;
    #pragma unroll
    for (int mi = 0; mi < 2; ++mi) {
        #pragma unroll
        for (int ni = 0; ni < 2; ++ni) {
            const int col = jb * 64 + n0 + ni * 8 + q4 * 2;
            const int x0 = ib * 64 + m0 + mi * 16 + gq;
            float2* d0 = (float2*)(Ms + (long)x0 * DD + col);
            float2* d8 = (float2*)(Ms + (long)(x0 + 8) * DD + col);
            float2 o0 = *d0, o8 = *d8;
            o0.x += C[mi][ni][0]; o0.y += C[mi][ni][1];
            o8.x += C[mi][ni][2]; o8.y += C[mi][ni][3];
            *d0 = o0; *d8 = o8;
        }
    }
}

// ---------------------------------------------------------------------------
// K3: retrieval via bf16x3 MMA, all operands pre-converted (pure copy staging).
// out[t][o] = sum_d q[t][d] * Ms[n][o][d]
// ---------------------------------------------------------------------------
__global__ __launch_bounds__(256) void k3_out(float* __restrict__ out)
{
    __shared__ unsigned sQh[64 * 36], sQl[64 * 36];
    __shared__ unsigned sMh[64 * 36], sMl[64 * 36];

    const int n   = blockIdx.y;
    const int tb  = blockIdx.x >> 2;
    const int ob  = blockIdx.x & 3;
    const int tid = threadIdx.x;
    const int wid = tid >> 5;
    const int lane = tid & 31;
    const int gq  = lane >> 2;
    const int q4  = lane & 3;

    const int m0 = (wid >> 2) * 32;
    const int n0 = (wid & 3) * 16;

    const int crow = tid >> 2;
    const int cseg = tid & 3;

    const long qw0 = ((long)tb * LL + (long)n * WW + crow) * (DD / 2) + cseg * 8;
    const long mw0 = (long)n * MATW + (long)(ob * 64 + crow) * (DD / 2) + cseg * 8;

    float C[2][2][4];
    #pragma unroll
    for (int mi = 0; mi < 2; ++mi)
        #pragma unroll
        for (int ni = 0; ni < 2; ++ni)
            #pragma unroll
            for (int e = 0; e < 4; ++e) C[mi][ni][e] = 0.f;

    for (int chu = 0; chu < 4; ++chu) {
        const int wbase = crow * 36 + cseg * 8;
        {
            uint4 a0 = *(const uint4*)(g_Qh + qw0 + chu * 32);
            uint4 a1 = *(const uint4*)(g_Qh + qw0 + chu * 32 + 4);
            uint4 l0 = *(const uint4*)(g_Ql + qw0 + chu * 32);
            uint4 l1 = *(const uint4*)(g_Ql + qw0 + chu * 32 + 4);
            sQh[wbase + 0] = a0.x; sQh[wbase + 1] = a0.y; sQh[wbase + 2] = a0.z; sQh[wbase + 3] = a0.w;
            sQh[wbase + 4] = a1.x; sQh[wbase + 5] = a1.y; sQh[wbase + 6] = a1.z; sQh[wbase + 7] = a1.w;
            sQl[wbase + 0] = l0.x; sQl[wbase + 1] = l0.y; sQl[wbase + 2] = l0.z; sQl[wbase + 3] = l0.w;
            sQl[wbase + 4] = l1.x; sQl[wbase + 5] = l1.y; sQl[wbase + 6] = l1.z; sQl[wbase + 7] = l1.w;
            uint4 b0 = *(const uint4*)(g_Msh + mw0 + chu * 32);
            uint4 b1 = *(const uint4*)(g_Msh + mw0 + chu * 32 + 4);
            uint4 m0v = *(const uint4*)(g_Msl + mw0 + chu * 32);
            uint4 m1v = *(const uint4*)(g_Msl + mw0 + chu * 32 + 4);
            sMh[wbase + 0] = b0.x; sMh[wbase + 1] = b0.y; sMh[wbase + 2] = b0.z; sMh[wbase + 3] = b0.w;
            sMh[wbase + 4] = b1.x; sMh[wbase + 5] = b1.y; sMh[wbase + 6] = b1.z; sMh[wbase + 7] = b1.w;
            sMl[wbase + 0] = m0v.x; sMl[wbase + 1] = m0v.y; sMl[wbase + 2] = m0v.z; sMl[wbase + 3] = m0v.w;
            sMl[wbase + 4] = m1v.x; sMl[wbase + 5] = m1v.y; sMl[wbase + 6] = m1v.z; sMl[wbase + 7] = m1v.w;
        }
        __syncthreads();

        #pragma unroll
        for (int ks = 0; ks < 4; ++ks) {
            const int kw = ks * 8;
            unsigned Ah[2][4], Al[2][4];
            #pragma unroll
            for (int mi = 0; mi < 2; ++mi) {
                const int r0 = (m0 + mi * 16 + gq) * 36 + kw + q4;
                const int r8 = (m0 + mi * 16 + gq + 8) * 36 + kw + q4;
                Ah[mi][0] = sQh[r0];     Ah[mi][1] = sQh[r8];
                Ah[mi][2] = sQh[r0 + 4]; Ah[mi][3] = sQh[r8 + 4];
                Al[mi][0] = sQl[r0];     Al[mi][1] = sQl[r8];
                Al[mi][2] = sQl[r0 + 4]; Al[mi][3] = sQl[r8 + 4];
            }
            unsigned Bh[2][2], Bl[2][2];
            #pragma unroll
            for (int ni = 0; ni < 2; ++ni) {
                const int rb = (n0 + ni * 8 + gq) * 36 + kw + q4;
                Bh[ni][0] = sMh[rb]; Bh[ni][1] = sMh[rb + 4];
                Bl[ni][0] = sMl[rb]; Bl[ni][1] = sMl[rb + 4];
            }
            #pragma unroll
            for (int mi = 0; mi < 2; ++mi)
                #pragma unroll
                for (int ni = 0; ni < 2; ++ni) {
                    mma_bf16(C[mi][ni], Ah[mi], Bh[ni]);
                    mma_bf16(C[mi][ni], Ah[mi], Bl[ni]);
                    mma_bf16(C[mi][ni], Al[mi], Bh[ni]);
                }
        }
        __syncthreads();
    }

    #pragma unroll
    for (int mi = 0; mi < 2; ++mi) {
        #pragma unroll
        for (int ni = 0; ni < 2; ++ni) {
            const int ocol = ob * 64 + n0 + ni * 8 + q4 * 2;
            const int tl0 = m0 + mi * 16 + gq;
            float* d0 = out + ((long)tb * LL + (long)n * WW + tl0) * DD + ocol;
            float* d8 = out + ((long)tb * LL + (long)n * WW + tl0 + 8) * DD + ocol;
            *(float2*)d0 = make_float2(C[mi][ni][0], C[mi][ni][1]);
            *(float2*)d8 = make_float2(C[mi][ni][2], C[mi][ni][3]);
        }
    }
}

// ---------------------------------------------------------------------------
extern "C" void kernel_launch(void* const* d_in, const int* in_sizes, int n_in,
                              void* d_out, int out_size)
{
    const float* keys    = (const float*)d_in[0];
    const float* values  = (const float*)d_in[1];
    const float* queries = (const float*)d_in[2];
    const float* gammas  = (const float*)d_in[3];
    const float* alpha   = (const float*)d_in[4];
    float* out = (float*)d_out;

    kConvQ<<<BB * LL * DD / 1024, 256>>>(queries);
    k1_moments<<<dim3(16, NW), 256>>>(keys, values, gammas);
    kA_local<<<dim3(64, CH), 256>>>(alpha);
    kTrP<<<dim3(64, NW - CS), dim3(32, 8)>>>();
    kT_init<<<dim3(64, CH), 256>>>();
    kT_combine<<<dim3(16, CH, 2), 256>>>(1, 0);  // buf0 -> buf1
    kT_combine<<<dim3(16, CH, 2), 256>>>(2, 1);  // buf1 -> buf0
    kT_combine<<<dim3(16, CH, 2), 256>>>(4, 0);  // buf0 -> buf1
    kT_combine<<<dim3(16, CH, 2), 256>>>(8, 1);  // buf1 -> buf0 (final: g_TS0)
    kTrE<<<CH * MATSZ / 1024, 256>>>();
    kC_fix<<<dim3(16, NW - CS), 256>>>();
    kConvM<<<NW * MATSZ / 1024, 256>>>();
    k3_out<<<dim3(32, NW), 256>>>(out);
}